// round 13
// baseline (speedup 1.0000x reference)
#include <cuda_runtime.h>
#include <cuda_bf16.h>
#include <cuda_fp16.h>
#include <cstdint>

#define NPTS 10000
#define KNB 32
#define KSZ 6
#define MCELLS 216           // 6*6*6
#define KD2 (MCELLS * 64)    // 13824
#define LDA1 896             // layer1 Kd=864 padded to 28*32
#define RPAD 10112           // 79 tiles * 128 rows
#define MT 79                // M tiles
#define NCH2 432             // KD2/32

// ---------------- device scratch (static: no allocs allowed) ----------------
__device__ float4 g_pairs[NPTS * KNB];
__device__ float  g_cnt[NPTS];
__device__ __align__(16) __half g_Af[(size_t)RPAD * KD2];   // A fp16 (279 MB), layer1 row-major / layers2-3 tiled
__device__ __align__(16) __half g_Wtf[64 * KD2];            // transposed W fp16 [Cout][lda]
__device__ __align__(16) __half g_Xh[NPTS * 64];            // layer activations fp16
__device__ float  g_acc[NPTS * 64];                         // fp32 accumulator
__device__ float  g_X3[NPTS * 32];
__device__ unsigned short g_offs[NPTS * 218];               // per-point per-cell slot offsets
__device__ unsigned long long g_recs[NPTS * 256];           // per-point sorted slot records {w fp32 | k}
__device__ int    g_mask_is_u8;

__device__ __forceinline__ float sgnf(float v) { return (v > 0.f) ? 1.f : ((v < 0.f) ? -1.f : 0.f); }

// ---------------- PTX helpers (all sm_80+ baseline; no 103a features) ----------------
__device__ __forceinline__ uint32_t smem_u32(const void* p) {
    uint32_t a;
    asm("{ .reg .u64 t; cvta.to.shared.u64 t, %1; cvt.u32.u64 %0, t; }" : "=r"(a) : "l"(p));
    return a;
}
__device__ __forceinline__ void cpa16(uint32_t dst, const void* src) {
    asm volatile("cp.async.cg.shared.global [%0], [%1], 16;" :: "r"(dst), "l"(src) : "memory");
}
__device__ __forceinline__ void ldmx4(uint32_t* r, uint32_t addr) {
    asm volatile("ldmatrix.sync.aligned.m8n8.x4.shared.b16 {%0,%1,%2,%3}, [%4];"
                 : "=r"(r[0]), "=r"(r[1]), "=r"(r[2]), "=r"(r[3]) : "r"(addr));
}
__device__ __forceinline__ void mma16816h(float* d, const uint32_t* a, uint32_t b0, uint32_t b1) {
    asm volatile(
        "mma.sync.aligned.m16n8k16.row.col.f32.f16.f16.f32 "
        "{%0,%1,%2,%3}, {%4,%5,%6,%7}, {%8,%9}, {%0,%1,%2,%3};"
        : "+f"(d[0]), "+f"(d[1]), "+f"(d[2]), "+f"(d[3])
        : "r"(a[0]), "r"(a[1]), "r"(a[2]), "r"(a[3]), "r"(b0), "r"(b1));
}

// ---------------- mask dtype detection ----------------
__global__ void detect_mask_kernel(const unsigned char* __restrict__ bytes) {
    int i = blockIdx.x * 256 + threadIdx.x;
    if (i >= NPTS * KNB) return;
    if ((i & 3) != 0 && bytes[i] != 0) atomicOr(&g_mask_is_u8, 1);
}
__device__ __forceinline__ unsigned read_mask(const void* m, int idx) {
    if (g_mask_is_u8) return ((const unsigned char*)m)[idx] ? 1u : 0u;
    return ((const int*)m)[idx] ? 1u : 0u;
}

// ---------------- geometry (+ fused wsplit of W1) ----------------
__global__ void geom_kernel(const float* __restrict__ pos, const int* __restrict__ nidx,
                            const void* __restrict__ nmask, const float* __restrict__ W1) {
    int idx = blockIdx.x * blockDim.x + threadIdx.x;

    if (idx < 64 * LDA1) {
        int o = idx / LDA1, k = idx - o * LDA1;
        float v = (k < MCELLS * 4) ? W1[(size_t)k * 64 + o] : 0.f;
        g_Wtf[(size_t)o * LDA1 + k] = __float2half_rn(v);
    }

    if (idx >= NPTS * KNB) return;
    int j = idx >> 5;
    int n = nidx[idx];
    unsigned m = read_mask(nmask, idx);

    const float EPS = 1e-12f;
    float x = (pos[n * 3 + 0] - pos[j * 3 + 0]) * (2.0f / 3.0f);
    float y = (pos[n * 3 + 1] - pos[j * 3 + 1]) * (2.0f / 3.0f);
    float z = (pos[n * 3 + 2] - pos[j * 3 + 2]) * (2.0f / 3.0f);

    float sq = x * x + y * y + z * z;
    float norm = sqrtf(fmaxf(sq, EPS));
    float rho2 = x * x + y * y;
    bool in_cone = (1.25f * z * z > rho2);
    float s, zc;
    if (in_cone) { s = sqrtf(3.0f * norm / (norm + fabsf(z))); zc = sgnf(z) * norm; }
    else         { s = norm / sqrtf(fmaxf(rho2, EPS));         zc = 1.5f * z; }
    float xc = x * s, yc = y * s;
    if (sq < EPS) { xc = 0.f; yc = 0.f; zc = 0.f; }

    float sq_xy = xc * xc + yc * yc;
    float norm_xy = sqrtf(fmaxf(sq_xy, EPS));
    bool x_major = fabsf(yc) <= fabsf(xc);
    float xd = (fabsf(xc) < EPS) ? 1.f : xc;
    float yd = (fabsf(yc) < EPS) ? 1.f : yc;
    float tx = sgnf(xc) * norm_xy, ty = sgnf(yc) * norm_xy;
    const float FOPI = 1.2732395447351628f;
    float xq, yq;
    if (x_major) { xq = tx;                        yq = tx * FOPI * atanf(yc / xd); }
    else         { xq = ty * FOPI * atanf(xc / yd); yq = ty; }
    if (sq_xy < EPS) { xq = 0.f; yq = 0.f; }

    float c0 = (xq + 1.f) * 2.5f, c1 = (yq + 1.f) * 2.5f, c2 = (zc + 1.f) * 2.5f;
    float f0 = floorf(c0), f1 = floorf(c1), f2 = floorf(c2);
    int i0x = min(max((int)f0, 0), KSZ - 1);
    int i0y = min(max((int)f1, 0), KSZ - 1);
    int i0z = min(max((int)f2, 0), KSZ - 1);
    unsigned packed = (unsigned)i0x | ((unsigned)i0y << 8) | ((unsigned)i0z << 16) | (m << 24);
    g_pairs[idx] = make_float4(__uint_as_float(packed), c0 - f0, c1 - f1, c2 - f2);
}

__global__ void count_kernel(const void* __restrict__ nmask) {
    int j = blockIdx.x * blockDim.x + threadIdx.x;
    if (j >= NPTS) return;
    int s = 0;
#pragma unroll
    for (int k = 0; k < KNB; k++) s += (int)read_mask(nmask, j * KNB + k);
    g_cnt[j] = (float)s;
}

// ---------------- W transpose (layers 2/3), fp16 ----------------
__global__ void wsplit_kernel(const float* __restrict__ W, int Kd, int Cout, int ldap) {
    int idx = blockIdx.x * 256 + threadIdx.x;
    if (idx >= Cout * ldap) return;
    int o = idx / ldap, k = idx - o * ldap;
    float v = (k < Kd) ? W[(size_t)k * Cout + o] : 0.f;
    g_Wtf[(size_t)o * ldap + k] = __float2half_rn(v);
}

// ---------------- sort: per-point slot records sorted by cell (deterministic) -------------
// block = 256 thr = 8 warps, one point per warp. Counting sort of the 256 (neighbor, corner)
// slots into cell order; serial lane-0 placement for run-to-run determinism.
__global__ void sort_kernel() {
    __shared__ unsigned bins[8][224];
    __shared__ unsigned char cellS[8][256];
    __shared__ float wF[8][256];
    int wid = threadIdx.x >> 5, lane = threadIdx.x & 31;
    int j = blockIdx.x * 8 + wid;
    if (j >= NPTS) return;
    for (int i = lane; i < 224; i += 32) bins[wid][i] = 0;
    __syncwarp();

    float4 p = g_pairs[j * KNB + lane];
    unsigned pk = __float_as_uint(p.x);
    int ix0 = pk & 255, iy0 = (pk >> 8) & 255, iz0 = (pk >> 16) & 255;
    float mk = (pk >> 24) ? 1.f : 0.f;
    int ix[2] = { ix0, min(ix0 + 1, KSZ - 1) };
    int iy[2] = { iy0, min(iy0 + 1, KSZ - 1) };
    int iz[2] = { iz0, min(iz0 + 1, KSZ - 1) };
    float wx[2] = { 1.f - p.y, p.y };
    float wy[2] = { 1.f - p.z, p.z };
    float wz[2] = { 1.f - p.w, p.w };
#pragma unroll
    for (int c8 = 0; c8 < 8; c8++) {
        int cx = c8 >> 2, cy = (c8 >> 1) & 1, cz = c8 & 1;
        int cell = (ix[cx] * KSZ + iy[cy]) * KSZ + iz[cz];
        cellS[wid][lane * 8 + c8] = (unsigned char)cell;
        wF[wid][lane * 8 + c8] = wx[cx] * wy[cy] * wz[cz] * mk;
        atomicAdd(&bins[wid][cell], 1u);
    }
    __syncwarp();

    // exclusive prefix over 216 bins
    unsigned carry = 0;
    for (int c = 0; c < 7; c++) {
        int idx = c * 32 + lane;
        unsigned v = (idx < MCELLS) ? bins[wid][idx] : 0;
        unsigned sc = v;
#pragma unroll
        for (int d = 1; d < 32; d <<= 1) {
            unsigned t = __shfl_up_sync(0xFFFFFFFFu, sc, d);
            if (lane >= d) sc += t;
        }
        if (idx < MCELLS) {
            unsigned excl = carry + sc - v;
            bins[wid][idx] = excl;
            g_offs[j * 218 + idx] = (unsigned short)excl;
        }
        carry += __shfl_sync(0xFFFFFFFFu, sc, 31);
    }
    if (lane == 0) g_offs[j * 218 + MCELLS] = 256;
    __syncwarp();

    // deterministic serial placement (lane 0)
    if (lane == 0) {
        for (int s = 0; s < 256; s++) {
            int cell = cellS[wid][s];
            unsigned pos = bins[wid][cell]++;
            unsigned w32 = __float_as_uint(wF[wid][s]);
            g_recs[(size_t)j * 256 + pos] =
                ((unsigned long long)w32 << 32) | (unsigned)(s >> 3);  // low = neighbor slot k
        }
    }
}

// ---------------- layer-1 scatter (CIN=4, smem-based, row-major A + fused acc zero) -------
__global__ void scatter4_kernel(const float* __restrict__ X, const int* __restrict__ nidx) {
    const int CIN = 4;
    extern __shared__ float sm[];
    float* A    = sm;                              // MCELLS*CIN
    float* feat = A + MCELLS * CIN;                // KNB*CIN
    float* wS   = feat + KNB * CIN;                // 256
    unsigned short* cellS = (unsigned short*)(wS + KNB * 8);

    int j = blockIdx.x;
    int tid = threadIdx.x;

    { int z = blockIdx.x * 256 + tid; if (z < NPTS * 64) g_acc[z] = 0.f; }

    for (int i = tid; i < MCELLS * CIN; i += 256) A[i] = 0.f;
    for (int i = tid; i < KNB * CIN; i += 256) {
        int k = i / CIN, c = i - k * CIN;
        feat[i] = X[(size_t)nidx[j * KNB + k] * CIN + c];
    }
    if (tid < KNB) {
        float4 p = g_pairs[j * KNB + tid];
        unsigned pk = __float_as_uint(p.x);
        int ix0 = pk & 255, iy0 = (pk >> 8) & 255, iz0 = (pk >> 16) & 255;
        float mk = (pk >> 24) ? 1.f : 0.f;
        int ix[2] = { ix0, min(ix0 + 1, KSZ - 1) };
        int iy[2] = { iy0, min(iy0 + 1, KSZ - 1) };
        int iz[2] = { iz0, min(iz0 + 1, KSZ - 1) };
        float wx[2] = { 1.f - p.y, p.y };
        float wy[2] = { 1.f - p.z, p.z };
        float wz[2] = { 1.f - p.w, p.w };
#pragma unroll
        for (int c8 = 0; c8 < 8; c8++) {
            int cx = c8 >> 2, cy = (c8 >> 1) & 1, cz = c8 & 1;
            cellS[tid * 8 + c8] = (unsigned short)((ix[cx] * KSZ + iy[cy]) * KSZ + iz[cz]);
            wS[tid * 8 + c8] = wx[cx] * wy[cy] * wz[cz] * mk;
        }
    }
    __syncthreads();

    for (int base = 0; base < KNB * 8 * CIN; base += 256) {
        int idx = base + tid;
        int p = idx / CIN, c = idx - p * CIN;
        float w = wS[p];
        if (w != 0.f) atomicAdd(&A[cellS[p] * CIN + c], w * feat[(p >> 3) * CIN + c]);
    }
    __syncthreads();

    // fp32 -> fp16, row-major lda = LDA1
    uint4* df = (uint4*)(g_Af + (size_t)j * LDA1);
    const int NV = MCELLS * CIN;
    for (int i = tid * 8; i < LDA1; i += 256 * 8) {
        uint32_t w[4];
#pragma unroll
        for (int p = 0; p < 4; p++) {
            int e = i + p * 2;
            float v0 = (e     < NV) ? A[e]     : 0.f;
            float v1 = (e + 1 < NV) ? A[e + 1] : 0.f;
            __half2 h2 = __floats2half2_rn(v0, v1);
            w[p] = *(uint32_t*)&h2;
        }
        __stcs(&df[i >> 3], make_uint4(w[0], w[1], w[2], w[3]));
    }
}

// ---------------- layers 2/3 scatter: register accumulation, tiled A output ---------------
// 2 blocks per point (cells [0,108) / [108,216)); thread = (cell, channel-half).
// No atomics, no smem A. Output chunk-tiled: [mt][kchunk][128 rows][32 k].
__global__ __launch_bounds__(256) void scatter64f_kernel(const int* __restrict__ nidx) {
    __shared__ __align__(16) char featS[32 * 144];   // 32 rows x 72 halfs (144 B stride)
    int tid = threadIdx.x;
    int j = blockIdx.x >> 1;
    int cbase = (blockIdx.x & 1) * 108;

    { int z = blockIdx.x * 256 + tid; if (z < NPTS * 64) g_acc[z] = 0.f; }

    // gather neighbor features (fp16)
    {
        int row = tid >> 3, sg = tid & 7;
        int nn = nidx[j * KNB + row];
        uint4 v = *((const uint4*)g_Xh + (size_t)nn * 8 + sg);
        *(uint4*)(featS + row * 144 + sg * 16) = v;
    }
    __syncthreads();

    if (tid >= 216) return;
    int cell = cbase + (tid >> 1);
    int half = tid & 1;
    int s0 = g_offs[j * 218 + cell];
    int s1 = g_offs[j * 218 + cell + 1];

    float acc[32];
#pragma unroll
    for (int i = 0; i < 32; i++) acc[i] = 0.f;

    const __half2* fS2 = (const __half2*)featS;
    for (int s = s0; s < s1; s++) {
        unsigned long long rec = g_recs[(size_t)j * 256 + s];
        float w = __uint_as_float((unsigned)(rec >> 32));
        int nbase = (int)(rec & 0xFFFFu) * 36 + half * 16;
#pragma unroll
        for (int i = 0; i < 16; i++) {
            float2 f2 = __half22float2(fS2[nbase + i]);
            acc[2 * i]     += w * f2.x;
            acc[2 * i + 1] += w * f2.y;
        }
    }

    uint32_t tmp[16];
#pragma unroll
    for (int i = 0; i < 16; i++) {
        __half2 h = __floats2half2_rn(acc[2 * i], acc[2 * i + 1]);
        tmp[i] = *(uint32_t*)&h;
    }
    int mt = j >> 7, r = j & 127;
    size_t off = ((size_t)(mt * NCH2 + 2 * cell + half) * 128 + r) * 32;
    uint4* dst = (uint4*)(g_Af + off);
    __stcs(dst + 0, make_uint4(tmp[0],  tmp[1],  tmp[2],  tmp[3]));
    __stcs(dst + 1, make_uint4(tmp[4],  tmp[5],  tmp[6],  tmp[7]));
    __stcs(dst + 2, make_uint4(tmp[8],  tmp[9],  tmp[10], tmp[11]));
    __stcs(dst + 3, make_uint4(tmp[12], tmp[13], tmp[14], tmp[15]));
}

// ---------------- persistent balanced fp16 mma.sync GEMM ----------------
#define NSTG 4
#define STG 15360
#define OFF_B 10240

template <int NC, bool TILED>
__launch_bounds__(256, 3)
__global__ void mma_kernel(int lda, int nch, int gridp) {
    extern __shared__ __align__(16) char smraw[];
    uint32_t sbase = smem_u32(smraw);
    int tid = threadIdx.x;
    int wid = tid >> 5, lane = tid & 31;

    int sel = lane >> 3, l8 = lane & 7;
    uint32_t aoff = (uint32_t)((wid * 16 + l8 + (sel & 1) * 8) * 80 + ((sel >> 1) * 8) * 2);
    uint32_t boff = (uint32_t)(((sel >> 1) * 8 + l8) * 80 + ((sel & 1) * 8) * 2);

    long total = (long)MT * nch;
    int g = blockIdx.x;
    int beg = (int)(total * g / gridp);
    int end = (int)(total * (g + 1) / gridp);
    int cnt = end - beg;
    if (cnt <= 0) return;

    float acc[NC / 8][4];
#pragma unroll
    for (int t = 0; t < NC / 8; t++)
#pragma unroll
        for (int q = 0; q < 4; q++) acc[t][q] = 0.f;

    auto load_stage = [&](int widx, int s) {
        uint32_t st = sbase + s * STG;
        int mt = widx / nch, kc = widx - mt * nch;
        if (TILED) {
            const char* base = (const char*)g_Af + ((size_t)mt * nch + kc) * 8192;
            for (int idx = tid; idx < 512; idx += 256)
                cpa16(st + (idx >> 2) * 80 + (idx & 3) * 16, base + (size_t)idx * 16);
        } else {
            int m0 = mt * 128;
            size_t k0 = (size_t)kc * 32;
            for (int idx = tid; idx < 512; idx += 256) {
                int r = idx >> 2, sg = idx & 3;
                cpa16(st + r * 80 + sg * 16,
                      (const char*)(g_Af + (size_t)(m0 + r) * lda + k0) + sg * 16);
            }
        }
        {
            int kc2 = widx - (widx / nch) * nch;
            size_t k0 = (size_t)kc2 * 32;
            for (int idx = tid; idx < NC * 4; idx += 256) {
                int o = idx >> 2, sg = idx & 3;
                cpa16(st + OFF_B + o * 80 + sg * 16,
                      (const char*)(g_Wtf + (size_t)o * lda + k0) + sg * 16);
            }
        }
        asm volatile("cp.async.commit_group;" ::: "memory");
    };

    auto compute = [&](int s) {
        uint32_t st = sbase + s * STG;
#pragma unroll
        for (int ks = 0; ks < 2; ks++) {
            uint32_t a[4];
            ldmx4(a, st + aoff + ks * 32);
#pragma unroll
            for (int ng = 0; ng < NC / 16; ng++) {
                uint32_t b[4];
                ldmx4(b, st + OFF_B + boff + (uint32_t)(ng * 16 * 80) + ks * 32);
                mma16816h(acc[2 * ng],     a, b[0], b[1]);
                mma16816h(acc[2 * ng + 1], a, b[2], b[3]);
            }
        }
    };

    auto flush = [&](int mt) {
        int m0 = mt * 128;
        int gg = lane >> 2, tg = lane & 3;
        int r0 = m0 + wid * 16 + gg;
        int r1 = r0 + 8;
#pragma unroll
        for (int nt = 0; nt < NC / 8; nt++) {
            int col = nt * 8 + tg * 2;
            if (r0 < NPTS) {
                atomicAdd(&g_acc[r0 * NC + col],     acc[nt][0]);
                atomicAdd(&g_acc[r0 * NC + col + 1], acc[nt][1]);
            }
            if (r1 < NPTS) {
                atomicAdd(&g_acc[r1 * NC + col],     acc[nt][2]);
                atomicAdd(&g_acc[r1 * NC + col + 1], acc[nt][3]);
            }
#pragma unroll
            for (int q = 0; q < 4; q++) acc[nt][q] = 0.f;
        }
    };

    int cur_mt = beg / nch;

    if (cnt < NSTG) {
        for (int p = 0; p < cnt; p++) load_stage(beg + p, p);
        asm volatile("cp.async.wait_group 0;" ::: "memory");
        __syncthreads();
        for (int i = 0; i < cnt; i++) {
            int mt = (beg + i) / nch;
            if (mt != cur_mt) { flush(cur_mt); cur_mt = mt; }
            compute(i);
        }
        flush(cur_mt);
        return;
    }

    for (int p = 0; p < NSTG - 1; p++) load_stage(beg + p, p);
    for (int i = 0; i < cnt; i++) {
        if (i + NSTG - 1 < cnt) load_stage(beg + i + NSTG - 1, (i + NSTG - 1) % NSTG);
        else asm volatile("cp.async.commit_group;" ::: "memory");
        asm volatile("cp.async.wait_group %0;" :: "n"(NSTG - 2) : "memory");
        __syncthreads();
        int mt = (beg + i) / nch;
        if (mt != cur_mt) { flush(cur_mt); cur_mt = mt; }
        compute(i % NSTG);
        __syncthreads();
    }
    flush(cur_mt);
}

// ---------------- finalize: normalize + bias + ReLU ----------------
__global__ void finalize_kernel(const float* __restrict__ bias, int Cout, int dst_sel) {
    int idx = blockIdx.x * 256 + threadIdx.x;
    if (idx >= NPTS * Cout) return;
    int j = idx / Cout, co = idx - j * Cout;
    float v = g_acc[idx];
    float c = g_cnt[j];
    if (c > 0.f) v /= c;
    v = fmaxf(v + bias[co], 0.f);
    if (dst_sel == 3) g_X3[idx] = v;
    else g_Xh[idx] = __float2half_rn(v);
}

// ---------------- fused FC chain: 32->64->64->32->3 ----------------
__global__ void fc_kernel(const float* __restrict__ Wf1, const float* __restrict__ bf1,
                          const float* __restrict__ Wf2, const float* __restrict__ bf2,
                          const float* __restrict__ Wf3, const float* __restrict__ bf3,
                          const float* __restrict__ Wo,  const float* __restrict__ bo,
                          float* __restrict__ out) {
    __shared__ float w1[32 * 64], w2[64 * 64], w3[64 * 32], wo[32 * 3];
    __shared__ float bb1[64], bb2[64], bb3[32], bbo[3];
    int tid = threadIdx.x;  // 128
    for (int i = tid; i < 2048; i += 128) w1[i] = Wf1[i];
    for (int i = tid; i < 4096; i += 128) w2[i] = Wf2[i];
    for (int i = tid; i < 2048; i += 128) w3[i] = Wf3[i];
    for (int i = tid; i < 96; i += 128) wo[i] = Wo[i];
    if (tid < 64) { bb1[tid] = bf1[tid]; bb2[tid] = bf2[tid]; }
    if (tid < 32) bb3[tid] = bf3[tid];
    if (tid < 3)  bbo[tid] = bo[tid];
    __syncthreads();

    int j = blockIdx.x * 128 + tid;
    if (j >= NPTS) return;

    float x[32];
#pragma unroll
    for (int i = 0; i < 32; i++) x[i] = g_X3[j * 32 + i];
    float y[64];
    for (int o = 0; o < 64; o++) {
        float s = bb1[o];
#pragma unroll
        for (int i = 0; i < 32; i++) s += x[i] * w1[i * 64 + o];
        y[o] = fmaxf(s, 0.f);
    }
    float z[64];
    for (int o = 0; o < 64; o++) {
        float s = bb2[o];
#pragma unroll
        for (int i = 0; i < 64; i++) s += y[i] * w2[i * 64 + o];
        z[o] = fmaxf(s, 0.f);
    }
    float t[32];
    for (int o = 0; o < 32; o++) {
        float s = bb3[o];
#pragma unroll
        for (int i = 0; i < 64; i++) s += z[i] * w3[i * 32 + o];
        t[o] = fmaxf(s, 0.f);
    }
    for (int o = 0; o < 3; o++) {
        float s = bbo[o];
#pragma unroll
        for (int i = 0; i < 32; i++) s += t[i] * wo[i * 3 + o];
        out[j * 3 + o] = s;
    }
}

// ---------------- launch ----------------
extern "C" void kernel_launch(void* const* d_in, const int* in_sizes, int n_in,
                              void* d_out, int out_size) {
    const float* feats = (const float*)d_in[0];
    const float* pos   = (const float*)d_in[1];
    const int*   nidx  = (const int*)d_in[2];
    const void*  nmask = d_in[3];
    const float* W1 = (const float*)d_in[4];  const float* b1 = (const float*)d_in[5];
    const float* W2 = (const float*)d_in[6];  const float* b2 = (const float*)d_in[7];
    const float* W3 = (const float*)d_in[8];  const float* b3 = (const float*)d_in[9];
    const float* Wf1 = (const float*)d_in[10]; const float* bf1 = (const float*)d_in[11];
    const float* Wf2 = (const float*)d_in[12]; const float* bf2 = (const float*)d_in[13];
    const float* Wf3 = (const float*)d_in[14]; const float* bf3 = (const float*)d_in[15];
    const float* Wo  = (const float*)d_in[16]; const float* bo  = (const float*)d_in[17];
    float* out = (float*)d_out;

    const int SMEM4 = (MCELLS * 4 + KNB * 4 + 256) * 4 + 512;
    const int SMEM_MMA = NSTG * STG;   // 61440 B
    cudaFuncSetAttribute(scatter4_kernel, cudaFuncAttributeMaxDynamicSharedMemorySize, SMEM4);
    cudaFuncSetAttribute(mma_kernel<64, false>, cudaFuncAttributeMaxDynamicSharedMemorySize, SMEM_MMA);
    cudaFuncSetAttribute(mma_kernel<64, true>,  cudaFuncAttributeMaxDynamicSharedMemorySize, SMEM_MMA);
    cudaFuncSetAttribute(mma_kernel<32, true>,  cudaFuncAttributeMaxDynamicSharedMemorySize, SMEM_MMA);

    int nsm = 148;
    cudaDeviceGetAttribute(&nsm, cudaDevAttrMultiProcessorCount, 0);
    int nb = 1;
    cudaOccupancyMaxActiveBlocksPerMultiprocessor(&nb, mma_kernel<64, true>, 256, SMEM_MMA);
    if (nb < 1) nb = 1;
    int gridm = nb * nsm;

    // ---- layer 1 (ncu capture window = my index 3 = mma<64,false>) ----
    detect_mask_kernel<<<(NPTS * KNB + 255) / 256, 256>>>((const unsigned char*)nmask);   // 0
    geom_kernel<<<(NPTS * KNB + 255) / 256, 256>>>(pos, nidx, nmask, W1);                 // 1
    scatter4_kernel<<<NPTS, 256, SMEM4>>>(feats, nidx);                                   // 2 (+zero acc)
    mma_kernel<64, false><<<gridm, 256, SMEM_MMA>>>(LDA1, LDA1 / 32, gridm);              // 3 <- profiled
    sort_kernel<<<(NPTS + 7) / 8, 256>>>();                                               // 4
    count_kernel<<<(NPTS + 255) / 256, 256>>>(nmask);                                     // 5
    finalize_kernel<<<(NPTS * 64 + 255) / 256, 256>>>(b1, 64, 1);                         // -> g_Xh

    // ---- layer 2: 64 -> 64 ----
    wsplit_kernel<<<(64 * KD2 + 255) / 256, 256>>>(W2, KD2, 64, KD2);
    scatter64f_kernel<<<NPTS * 2, 256>>>(nidx);                                           // (+zero acc)
    mma_kernel<64, true><<<gridm, 256, SMEM_MMA>>>(KD2, NCH2, gridm);
    finalize_kernel<<<(NPTS * 64 + 255) / 256, 256>>>(b2, 64, 2);                         // -> g_Xh

    // ---- layer 3: 64 -> 32 ----
    wsplit_kernel<<<(32 * KD2 + 255) / 256, 256>>>(W3, KD2, 32, KD2);
    scatter64f_kernel<<<NPTS * 2, 256>>>(nidx);                                           // (+zero acc)
    mma_kernel<32, true><<<gridm, 256, SMEM_MMA>>>(KD2, NCH2, gridm);
    finalize_kernel<<<(NPTS * 32 + 255) / 256, 256>>>(b3, 32, 3);                         // -> g_X3

    // FC head
    fc_kernel<<<(NPTS + 127) / 128, 128>>>(Wf1, bf1, Wf2, bf2, Wf3, bf3, Wo, bo, out);
}

// round 15
// speedup vs baseline: 1.1666x; 1.1666x over previous
#include <cuda_runtime.h>
#include <cuda_bf16.h>
#include <cuda_fp16.h>
#include <cstdint>

#define NPTS 10000
#define KNB 32
#define KSZ 6
#define MCELLS 216           // 6*6*6
#define KD2 (MCELLS * 64)    // 13824
#define LDA1 896             // layer1 Kd=864 padded to 28*32
#define RPAD 10112           // 79 tiles * 128 rows
#define MT 79                // M tiles

// ---------------- device scratch (static: no allocs allowed) ----------------
__device__ float4 g_pairs[NPTS * KNB];
__device__ float  g_cnt[NPTS];
__device__ __align__(16) __half g_Af[(size_t)RPAD * KD2];   // scatter output fp16 (277 MB)
__device__ __align__(16) __half g_Wtf[64 * KD2];            // transposed W fp16 [Cout][lda]
__device__ float  g_acc[NPTS * 64];                         // fp32 accumulator
__device__ float  g_X1[NPTS * 64];
__device__ float  g_X2[NPTS * 64];
__device__ float  g_X3[NPTS * 32];
__device__ int    g_mask_is_u8;

__device__ __forceinline__ float sgnf(float v) { return (v > 0.f) ? 1.f : ((v < 0.f) ? -1.f : 0.f); }

// ---------------- PTX helpers (all sm_80+ baseline; no 103a features) ----------------
__device__ __forceinline__ uint32_t smem_u32(const void* p) {
    uint32_t a;
    asm("{ .reg .u64 t; cvta.to.shared.u64 t, %1; cvt.u32.u64 %0, t; }" : "=r"(a) : "l"(p));
    return a;
}
__device__ __forceinline__ void cpa16(uint32_t dst, const void* src) {
    asm volatile("cp.async.cg.shared.global [%0], [%1], 16;" :: "r"(dst), "l"(src) : "memory");
}
__device__ __forceinline__ void ldmx4(uint32_t* r, uint32_t addr) {
    asm volatile("ldmatrix.sync.aligned.m8n8.x4.shared.b16 {%0,%1,%2,%3}, [%4];"
                 : "=r"(r[0]), "=r"(r[1]), "=r"(r[2]), "=r"(r[3]) : "r"(addr));
}
__device__ __forceinline__ void mma16816h(float* d, const uint32_t* a, uint32_t b0, uint32_t b1) {
    asm volatile(
        "mma.sync.aligned.m16n8k16.row.col.f32.f16.f16.f32 "
        "{%0,%1,%2,%3}, {%4,%5,%6,%7}, {%8,%9}, {%0,%1,%2,%3};"
        : "+f"(d[0]), "+f"(d[1]), "+f"(d[2]), "+f"(d[3])
        : "r"(a[0]), "r"(a[1]), "r"(a[2]), "r"(a[3]), "r"(b0), "r"(b1));
}

// ---------------- mask dtype detection ----------------
__global__ void detect_mask_kernel(const unsigned char* __restrict__ bytes) {
    int i = blockIdx.x * 256 + threadIdx.x;
    if (i >= NPTS * KNB) return;
    if ((i & 3) != 0 && bytes[i] != 0) atomicOr(&g_mask_is_u8, 1);
}
__device__ __forceinline__ unsigned read_mask(const void* m, int idx) {
    if (g_mask_is_u8) return ((const unsigned char*)m)[idx] ? 1u : 0u;
    return ((const int*)m)[idx] ? 1u : 0u;
}

// ---------------- geometry (+ fused wsplit of W1) ----------------
__global__ void geom_kernel(const float* __restrict__ pos, const int* __restrict__ nidx,
                            const void* __restrict__ nmask, const float* __restrict__ W1) {
    int idx = blockIdx.x * blockDim.x + threadIdx.x;

    if (idx < 64 * LDA1) {
        int o = idx / LDA1, k = idx - o * LDA1;
        float v = (k < MCELLS * 4) ? W1[(size_t)k * 64 + o] : 0.f;
        g_Wtf[(size_t)o * LDA1 + k] = __float2half_rn(v);
    }

    if (idx >= NPTS * KNB) return;
    int j = idx >> 5;
    int n = nidx[idx];
    unsigned m = read_mask(nmask, idx);

    const float EPS = 1e-12f;
    float x = (pos[n * 3 + 0] - pos[j * 3 + 0]) * (2.0f / 3.0f);
    float y = (pos[n * 3 + 1] - pos[j * 3 + 1]) * (2.0f / 3.0f);
    float z = (pos[n * 3 + 2] - pos[j * 3 + 2]) * (2.0f / 3.0f);

    float sq = x * x + y * y + z * z;
    float norm = sqrtf(fmaxf(sq, EPS));
    float rho2 = x * x + y * y;
    bool in_cone = (1.25f * z * z > rho2);
    float s, zc;
    if (in_cone) { s = sqrtf(3.0f * norm / (norm + fabsf(z))); zc = sgnf(z) * norm; }
    else         { s = norm / sqrtf(fmaxf(rho2, EPS));         zc = 1.5f * z; }
    float xc = x * s, yc = y * s;
    if (sq < EPS) { xc = 0.f; yc = 0.f; zc = 0.f; }

    float sq_xy = xc * xc + yc * yc;
    float norm_xy = sqrtf(fmaxf(sq_xy, EPS));
    bool x_major = fabsf(yc) <= fabsf(xc);
    float xd = (fabsf(xc) < EPS) ? 1.f : xc;
    float yd = (fabsf(yc) < EPS) ? 1.f : yc;
    float tx = sgnf(xc) * norm_xy, ty = sgnf(yc) * norm_xy;
    const float FOPI = 1.2732395447351628f;
    float xq, yq;
    if (x_major) { xq = tx;                        yq = tx * FOPI * atanf(yc / xd); }
    else         { xq = ty * FOPI * atanf(xc / yd); yq = ty; }
    if (sq_xy < EPS) { xq = 0.f; yq = 0.f; }

    float c0 = (xq + 1.f) * 2.5f, c1 = (yq + 1.f) * 2.5f, c2 = (zc + 1.f) * 2.5f;
    float f0 = floorf(c0), f1 = floorf(c1), f2 = floorf(c2);
    int i0x = min(max((int)f0, 0), KSZ - 1);
    int i0y = min(max((int)f1, 0), KSZ - 1);
    int i0z = min(max((int)f2, 0), KSZ - 1);
    unsigned packed = (unsigned)i0x | ((unsigned)i0y << 8) | ((unsigned)i0z << 16) | (m << 24);
    g_pairs[idx] = make_float4(__uint_as_float(packed), c0 - f0, c1 - f1, c2 - f2);
}

__global__ void count_kernel(const void* __restrict__ nmask) {
    int j = blockIdx.x * blockDim.x + threadIdx.x;
    if (j >= NPTS) return;
    int s = 0;
#pragma unroll
    for (int k = 0; k < KNB; k++) s += (int)read_mask(nmask, j * KNB + k);
    g_cnt[j] = (float)s;
}

// ---------------- W transpose (layers 2/3), fp16 ----------------
__global__ void wsplit_kernel(const float* __restrict__ W, int Kd, int Cout, int ldap) {
    int idx = blockIdx.x * 256 + threadIdx.x;
    if (idx >= Cout * ldap) return;
    int o = idx / ldap, k = idx - o * ldap;
    float v = (k < Kd) ? W[(size_t)k * Cout + o] : 0.f;
    g_Wtf[(size_t)o * ldap + k] = __float2half_rn(v);
}

// ---------------- scatter (+ fused g_acc zeroing): build A in shared, emit fp16 ----------------
template <int CIN>
__global__ void scatter_kernel(const float* __restrict__ X, const int* __restrict__ nidx,
                               int src_sel, int lda) {
    extern __shared__ float sm[];
    float* A    = sm;                              // MCELLS*CIN
    float* feat = A + MCELLS * CIN;                // KNB*CIN
    float* wS   = feat + KNB * CIN;                // 256
    unsigned short* cellS = (unsigned short*)(wS + KNB * 8);

    const float* __restrict__ src = (src_sel == 1) ? g_X1 : ((src_sel == 2) ? g_X2 : X);
    int j = blockIdx.x;
    int tid = threadIdx.x;

    { int z = blockIdx.x * 256 + tid; if (z < NPTS * 64) g_acc[z] = 0.f; }

    for (int i = tid; i < MCELLS * CIN; i += 256) A[i] = 0.f;
    for (int i = tid; i < KNB * CIN; i += 256) {
        int k = i / CIN, c = i - k * CIN;
        feat[i] = src[(size_t)nidx[j * KNB + k] * CIN + c];
    }
    if (tid < KNB) {
        float4 p = g_pairs[j * KNB + tid];
        unsigned pk = __float_as_uint(p.x);
        int ix0 = pk & 255, iy0 = (pk >> 8) & 255, iz0 = (pk >> 16) & 255;
        float mk = (pk >> 24) ? 1.f : 0.f;
        int ix[2] = { ix0, min(ix0 + 1, KSZ - 1) };
        int iy[2] = { iy0, min(iy0 + 1, KSZ - 1) };
        int iz[2] = { iz0, min(iz0 + 1, KSZ - 1) };
        float wx[2] = { 1.f - p.y, p.y };
        float wy[2] = { 1.f - p.z, p.z };
        float wz[2] = { 1.f - p.w, p.w };
#pragma unroll
        for (int c8 = 0; c8 < 8; c8++) {
            int cx = c8 >> 2, cy = (c8 >> 1) & 1, cz = c8 & 1;
            cellS[tid * 8 + c8] = (unsigned short)((ix[cx] * KSZ + iy[cy]) * KSZ + iz[cz]);
            wS[tid * 8 + c8] = wx[cx] * wy[cy] * wz[cz] * mk;
        }
    }
    __syncthreads();

    for (int base = 0; base < KNB * 8 * CIN; base += 256) {
        int idx = base + tid;
        int p = idx / CIN, c = idx - p * CIN;
        float w = wS[p];
        if (w != 0.f) atomicAdd(&A[cellS[p] * CIN + c], w * feat[(p >> 3) * CIN + c]);
    }
    __syncthreads();

    // fp32 -> fp16, 8 values per 16B streaming store
    uint4* df = (uint4*)(g_Af + (size_t)j * lda);
    const int NV = MCELLS * CIN;
    for (int i = tid * 8; i < lda; i += 256 * 8) {
        uint32_t w[4];
#pragma unroll
        for (int p = 0; p < 4; p++) {
            int e = i + p * 2;
            float v0 = (e     < NV) ? A[e]     : 0.f;
            float v1 = (e + 1 < NV) ? A[e + 1] : 0.f;
            __half2 h2 = __floats2half2_rn(v0, v1);
            w[p] = *(uint32_t*)&h2;
        }
        __stcs(&df[i >> 3], make_uint4(w[0], w[1], w[2], w[3]));
    }
}

// ---------------- persistent balanced fp16 mma.sync GEMM (single product) ----------------
// Fixed grid; each CTA walks a contiguous range of the flattened (mtile, kchunk)
// work list, register-accumulating, atomic-flushing at mtile boundaries.
// CTA: 256 thr / 8 warps; mtile = 128 rows; k chunk = 32.
// 4-stage cp.async ring with SINGLE sync per chunk:
//   wait(NSTG-2) -> sync -> compute(i) -> load(i+NSTG-1)
// (load i+3 writes buffer (i-1)%4; sync at iter i guarantees all warps left compute(i-1))
#define NSTG 4
#define STG 15360
#define OFF_B 10240

template <int NC>
__launch_bounds__(256, 3)
__global__ void mma_kernel(int lda, int nch, int gridp) {
    extern __shared__ __align__(16) char smraw[];
    uint32_t sbase = smem_u32(smraw);
    int tid = threadIdx.x;
    int wid = tid >> 5, lane = tid & 31;

    int sel = lane >> 3, l8 = lane & 7;
    uint32_t aoff = (uint32_t)((wid * 16 + l8 + (sel & 1) * 8) * 80 + ((sel >> 1) * 8) * 2);
    uint32_t boff = (uint32_t)(((sel >> 1) * 8 + l8) * 80 + ((sel & 1) * 8) * 2);

    long total = (long)MT * nch;
    int g = blockIdx.x;
    int beg = (int)(total * g / gridp);
    int end = (int)(total * (g + 1) / gridp);
    int cnt = end - beg;
    if (cnt <= 0) return;

    float acc[NC / 8][4];
#pragma unroll
    for (int t = 0; t < NC / 8; t++)
#pragma unroll
        for (int q = 0; q < 4; q++) acc[t][q] = 0.f;

    auto load_stage = [&](int widx, int s) {
        uint32_t st = sbase + s * STG;
        int mt = widx / nch, kc = widx - mt * nch;
        int m0 = mt * 128;
        size_t k0 = (size_t)kc * 32;
        for (int idx = tid; idx < 512; idx += 256) {
            int r = idx >> 2, sg = idx & 3;
            cpa16(st + r * 80 + sg * 16,
                  (const char*)(g_Af + (size_t)(m0 + r) * lda + k0) + sg * 16);
        }
        for (int idx = tid; idx < NC * 4; idx += 256) {
            int o = idx >> 2, sg = idx & 3;
            cpa16(st + OFF_B + o * 80 + sg * 16,
                  (const char*)(g_Wtf + (size_t)o * lda + k0) + sg * 16);
        }
        asm volatile("cp.async.commit_group;" ::: "memory");
    };

    auto compute = [&](int s) {
        uint32_t st = sbase + s * STG;
#pragma unroll
        for (int ks = 0; ks < 2; ks++) {
            uint32_t a[4];
            ldmx4(a, st + aoff + ks * 32);
#pragma unroll
            for (int ng = 0; ng < NC / 16; ng++) {
                uint32_t b[4];
                ldmx4(b, st + OFF_B + boff + (uint32_t)(ng * 16 * 80) + ks * 32);
                mma16816h(acc[2 * ng],     a, b[0], b[1]);
                mma16816h(acc[2 * ng + 1], a, b[2], b[3]);
            }
        }
    };

    auto flush = [&](int mt) {
        int m0 = mt * 128;
        int gg = lane >> 2, tg = lane & 3;
        int r0 = m0 + wid * 16 + gg;
        int r1 = r0 + 8;
#pragma unroll
        for (int nt = 0; nt < NC / 8; nt++) {
            int col = nt * 8 + tg * 2;
            if (r0 < NPTS) {
                atomicAdd(&g_acc[r0 * NC + col],     acc[nt][0]);
                atomicAdd(&g_acc[r0 * NC + col + 1], acc[nt][1]);
            }
            if (r1 < NPTS) {
                atomicAdd(&g_acc[r1 * NC + col],     acc[nt][2]);
                atomicAdd(&g_acc[r1 * NC + col + 1], acc[nt][3]);
            }
#pragma unroll
            for (int q = 0; q < 4; q++) acc[nt][q] = 0.f;
        }
    };

    int cur_mt = beg / nch;

    if (cnt < NSTG) {
        for (int p = 0; p < cnt; p++) load_stage(beg + p, p);
        asm volatile("cp.async.wait_group 0;" ::: "memory");
        __syncthreads();
        for (int i = 0; i < cnt; i++) {
            int mt = (beg + i) / nch;
            if (mt != cur_mt) { flush(cur_mt); cur_mt = mt; }
            compute(i);
        }
        flush(cur_mt);
        return;
    }

    // prologue: stages 0 .. NSTG-2
    for (int p = 0; p < NSTG - 1; p++) load_stage(beg + p, p);
    for (int i = 0; i < cnt; i++) {
        asm volatile("cp.async.wait_group %0;" :: "n"(NSTG - 2) : "memory");
        __syncthreads();
        int mt = (beg + i) / nch;
        if (mt != cur_mt) { flush(cur_mt); cur_mt = mt; }
        compute(i % NSTG);
        if (i + NSTG - 1 < cnt) load_stage(beg + i + NSTG - 1, (i + NSTG - 1) % NSTG);
        else asm volatile("cp.async.commit_group;" ::: "memory");
    }
    flush(cur_mt);
}

// ---------------- finalize: normalize by neighbor count, + bias, ReLU ----------------
__global__ void finalize_kernel(const float* __restrict__ bias, int Cout, int dst_sel) {
    int idx = blockIdx.x * 256 + threadIdx.x;
    if (idx >= NPTS * Cout) return;
    int j = idx / Cout, co = idx - j * Cout;
    float v = g_acc[idx];
    float c = g_cnt[j];
    if (c > 0.f) v /= c;
    v = fmaxf(v + bias[co], 0.f);
    if (dst_sel == 1) g_X1[idx] = v;
    else if (dst_sel == 2) g_X2[idx] = v;
    else g_X3[idx] = v;
}

// ---------------- fused FC chain: 32->64->64->32->3 ----------------
__global__ void fc_kernel(const float* __restrict__ Wf1, const float* __restrict__ bf1,
                          const float* __restrict__ Wf2, const float* __restrict__ bf2,
                          const float* __restrict__ Wf3, const float* __restrict__ bf3,
                          const float* __restrict__ Wo,  const float* __restrict__ bo,
                          float* __restrict__ out) {
    __shared__ float w1[32 * 64], w2[64 * 64], w3[64 * 32], wo[32 * 3];
    __shared__ float bb1[64], bb2[64], bb3[32], bbo[3];
    int tid = threadIdx.x;  // 128
    for (int i = tid; i < 2048; i += 128) w1[i] = Wf1[i];
    for (int i = tid; i < 4096; i += 128) w2[i] = Wf2[i];
    for (int i = tid; i < 2048; i += 128) w3[i] = Wf3[i];
    for (int i = tid; i < 96; i += 128) wo[i] = Wo[i];
    if (tid < 64) { bb1[tid] = bf1[tid]; bb2[tid] = bf2[tid]; }
    if (tid < 32) bb3[tid] = bf3[tid];
    if (tid < 3)  bbo[tid] = bo[tid];
    __syncthreads();

    int j = blockIdx.x * 128 + tid;
    if (j >= NPTS) return;

    float x[32];
#pragma unroll
    for (int i = 0; i < 32; i++) x[i] = g_X3[j * 32 + i];
    float y[64];
    for (int o = 0; o < 64; o++) {
        float s = bb1[o];
#pragma unroll
        for (int i = 0; i < 32; i++) s += x[i] * w1[i * 64 + o];
        y[o] = fmaxf(s, 0.f);
    }
    float z[64];
    for (int o = 0; o < 64; o++) {
        float s = bb2[o];
#pragma unroll
        for (int i = 0; i < 64; i++) s += y[i] * w2[i * 64 + o];
        z[o] = fmaxf(s, 0.f);
    }
    float t[32];
    for (int o = 0; o < 32; o++) {
        float s = bb3[o];
#pragma unroll
        for (int i = 0; i < 64; i++) s += z[i] * w3[i * 32 + o];
        t[o] = fmaxf(s, 0.f);
    }
    for (int o = 0; o < 3; o++) {
        float s = bbo[o];
#pragma unroll
        for (int i = 0; i < 32; i++) s += t[i] * wo[i * 3 + o];
        out[j * 3 + o] = s;
    }
}

// ---------------- launch ----------------
extern "C" void kernel_launch(void* const* d_in, const int* in_sizes, int n_in,
                              void* d_out, int out_size) {
    const float* feats = (const float*)d_in[0];
    const float* pos   = (const float*)d_in[1];
    const int*   nidx  = (const int*)d_in[2];
    const void*  nmask = d_in[3];
    const float* W1 = (const float*)d_in[4];  const float* b1 = (const float*)d_in[5];
    const float* W2 = (const float*)d_in[6];  const float* b2 = (const float*)d_in[7];
    const float* W3 = (const float*)d_in[8];  const float* b3 = (const float*)d_in[9];
    const float* Wf1 = (const float*)d_in[10]; const float* bf1 = (const float*)d_in[11];
    const float* Wf2 = (const float*)d_in[12]; const float* bf2 = (const float*)d_in[13];
    const float* Wf3 = (const float*)d_in[14]; const float* bf3 = (const float*)d_in[15];
    const float* Wo  = (const float*)d_in[16]; const float* bo  = (const float*)d_in[17];
    float* out = (float*)d_out;

    const int SMEM64 = (MCELLS * 64 + KNB * 64 + 256) * 4 + 512;
    const int SMEM4  = (MCELLS * 4  + KNB * 4  + 256) * 4 + 512;
    const int SMEM_MMA = NSTG * STG;   // 61440 B -> 3 CTAs/SM
    cudaFuncSetAttribute(scatter_kernel<64>, cudaFuncAttributeMaxDynamicSharedMemorySize, SMEM64);
    cudaFuncSetAttribute(scatter_kernel<4>,  cudaFuncAttributeMaxDynamicSharedMemorySize, SMEM4);
    cudaFuncSetAttribute(mma_kernel<64>, cudaFuncAttributeMaxDynamicSharedMemorySize, SMEM_MMA);
    cudaFuncSetAttribute(mma_kernel<32>, cudaFuncAttributeMaxDynamicSharedMemorySize, SMEM_MMA);

    int nsm = 148;
    cudaDeviceGetAttribute(&nsm, cudaDevAttrMultiProcessorCount, 0);
    int nb64 = 1, nb32 = 1;
    cudaOccupancyMaxActiveBlocksPerMultiprocessor(&nb64, mma_kernel<64>, 256, SMEM_MMA);
    cudaOccupancyMaxActiveBlocksPerMultiprocessor(&nb32, mma_kernel<32>, 256, SMEM_MMA);
    if (nb64 < 1) nb64 = 1;
    if (nb32 < 1) nb32 = 1;
    int grid64 = nb64 * nsm, grid32 = nb32 * nsm;

    // ---- layer 1 (ncu capture window = my index 3 = mma_kernel<64>) ----
    detect_mask_kernel<<<(NPTS * KNB + 255) / 256, 256>>>((const unsigned char*)nmask);   // 0
    geom_kernel<<<(NPTS * KNB + 255) / 256, 256>>>(pos, nidx, nmask, W1);                 // 1 (+wsplit W1)
    scatter_kernel<4><<<NPTS, 256, SMEM4>>>(feats, nidx, 0, LDA1);                        // 2 (+zero acc)
    mma_kernel<64><<<grid64, 256, SMEM_MMA>>>(LDA1, LDA1 / 32, grid64);                   // 3 <- profiled
    count_kernel<<<(NPTS + 255) / 256, 256>>>(nmask);
    finalize_kernel<<<(NPTS * 64 + 255) / 256, 256>>>(b1, 64, 1);

    // ---- layer 2: 64 -> 64, lda = 13824 (432 chunks) ----
    wsplit_kernel<<<(64 * KD2 + 255) / 256, 256>>>(W2, KD2, 64, KD2);
    scatter_kernel<64><<<NPTS, 256, SMEM64>>>(nullptr, nidx, 1, KD2);
    mma_kernel<64><<<grid64, 256, SMEM_MMA>>>(KD2, KD2 / 32, grid64);
    finalize_kernel<<<(NPTS * 64 + 255) / 256, 256>>>(b2, 64, 2);

    // ---- layer 3: 64 -> 32 ----
    wsplit_kernel<<<(32 * KD2 + 255) / 256, 256>>>(W3, KD2, 32, KD2);
    scatter_kernel<64><<<NPTS, 256, SMEM64>>>(nullptr, nidx, 2, KD2);
    mma_kernel<32><<<grid32, 256, SMEM_MMA>>>(KD2, KD2 / 32, grid32);
    finalize_kernel<<<(NPTS * 32 + 255) / 256, 256>>>(b3, 32, 3);

    // FC head
    fc_kernel<<<(NPTS + 127) / 128, 128>>>(Wf1, bf1, Wf2, bf2, Wf3, bf3, Wo, bo, out);
}

// round 16
// speedup vs baseline: 1.4022x; 1.2020x over previous
#include <cuda_runtime.h>
#include <cuda_bf16.h>
#include <cuda_fp16.h>
#include <cstdint>

#define NPTS 10000
#define KNB 32
#define KSZ 6
#define MCELLS 216           // 6*6*6
#define KD2 (MCELLS * 64)    // 13824
#define LDA1 896             // layer1 Kd=864 padded to 28*32
#define RPAD 10112           // 79 tiles * 128 rows
#define MT 79                // M tiles
#define NCH2 432             // KD2/32

// ---------------- device scratch (static: no allocs allowed) ----------------
__device__ float4 g_pairs[NPTS * KNB];
__device__ float  g_cnt[NPTS];
__device__ __align__(16) __half g_Af[(size_t)RPAD * LDA1];  // layer-1 A fp16 (18 MB)
__device__ __align__(16) __half g_Wtf[64 * KD2];            // transposed W fp16 [Cout][lda]
__device__ __align__(16) __half g_Xh[NPTS * 64];            // activations fp16 (layer in/out)
__device__ float  g_acc[NPTS * 64];                         // fp32 accumulator (zeroed by finalize chain)
__device__ float  g_X3[NPTS * 32];
__device__ unsigned short g_offs[NPTS * 218];               // per-point per-cell slot offsets
__device__ unsigned long long g_recs[NPTS * 256];           // sorted slot records {w fp32 | n u16}
__device__ int    g_mask_is_u8;

__device__ __forceinline__ float sgnf(float v) { return (v > 0.f) ? 1.f : ((v < 0.f) ? -1.f : 0.f); }

// ---------------- PTX helpers (all sm_80+ baseline; no 103a features) ----------------
__device__ __forceinline__ uint32_t smem_u32(const void* p) {
    uint32_t a;
    asm("{ .reg .u64 t; cvta.to.shared.u64 t, %1; cvt.u32.u64 %0, t; }" : "=r"(a) : "l"(p));
    return a;
}
__device__ __forceinline__ void cpa16(uint32_t dst, const void* src) {
    asm volatile("cp.async.cg.shared.global [%0], [%1], 16;" :: "r"(dst), "l"(src) : "memory");
}
#define STS128A(addr, a, b, c, d) \
    asm volatile("st.shared.v4.b32 [%0], {%1,%2,%3,%4};" :: "r"(addr), "r"(a), "r"(b), "r"(c), "r"(d) : "memory")
__device__ __forceinline__ void ldmx4(uint32_t* r, uint32_t addr) {
    asm volatile("ldmatrix.sync.aligned.m8n8.x4.shared.b16 {%0,%1,%2,%3}, [%4];"
                 : "=r"(r[0]), "=r"(r[1]), "=r"(r[2]), "=r"(r[3]) : "r"(addr));
}
__device__ __forceinline__ void mma16816h(float* d, const uint32_t* a, uint32_t b0, uint32_t b1) {
    asm volatile(
        "mma.sync.aligned.m16n8k16.row.col.f32.f16.f16.f32 "
        "{%0,%1,%2,%3}, {%4,%5,%6,%7}, {%8,%9}, {%0,%1,%2,%3};"
        : "+f"(d[0]), "+f"(d[1]), "+f"(d[2]), "+f"(d[3])
        : "r"(a[0]), "r"(a[1]), "r"(a[2]), "r"(a[3]), "r"(b0), "r"(b1));
}

// ---------------- mask dtype detection ----------------
__global__ void detect_mask_kernel(const unsigned char* __restrict__ bytes) {
    int i = blockIdx.x * 256 + threadIdx.x;
    if (i >= NPTS * KNB) return;
    if ((i & 3) != 0 && bytes[i] != 0) atomicOr(&g_mask_is_u8, 1);
}
__device__ __forceinline__ unsigned read_mask(const void* m, int idx) {
    if (g_mask_is_u8) return ((const unsigned char*)m)[idx] ? 1u : 0u;
    return ((const int*)m)[idx] ? 1u : 0u;
}

// ---------------- geometry (+ fused wsplit of W1) ----------------
__global__ void geom_kernel(const float* __restrict__ pos, const int* __restrict__ nidx,
                            const void* __restrict__ nmask, const float* __restrict__ W1) {
    int idx = blockIdx.x * blockDim.x + threadIdx.x;

    if (idx < 64 * LDA1) {
        int o = idx / LDA1, k = idx - o * LDA1;
        float v = (k < MCELLS * 4) ? W1[(size_t)k * 64 + o] : 0.f;
        g_Wtf[(size_t)o * LDA1 + k] = __float2half_rn(v);
    }

    if (idx >= NPTS * KNB) return;
    int j = idx >> 5;
    int n = nidx[idx];
    unsigned m = read_mask(nmask, idx);

    const float EPS = 1e-12f;
    float x = (pos[n * 3 + 0] - pos[j * 3 + 0]) * (2.0f / 3.0f);
    float y = (pos[n * 3 + 1] - pos[j * 3 + 1]) * (2.0f / 3.0f);
    float z = (pos[n * 3 + 2] - pos[j * 3 + 2]) * (2.0f / 3.0f);

    float sq = x * x + y * y + z * z;
    float norm = sqrtf(fmaxf(sq, EPS));
    float rho2 = x * x + y * y;
    bool in_cone = (1.25f * z * z > rho2);
    float s, zc;
    if (in_cone) { s = sqrtf(3.0f * norm / (norm + fabsf(z))); zc = sgnf(z) * norm; }
    else         { s = norm / sqrtf(fmaxf(rho2, EPS));         zc = 1.5f * z; }
    float xc = x * s, yc = y * s;
    if (sq < EPS) { xc = 0.f; yc = 0.f; zc = 0.f; }

    float sq_xy = xc * xc + yc * yc;
    float norm_xy = sqrtf(fmaxf(sq_xy, EPS));
    bool x_major = fabsf(yc) <= fabsf(xc);
    float xd = (fabsf(xc) < EPS) ? 1.f : xc;
    float yd = (fabsf(yc) < EPS) ? 1.f : yc;
    float tx = sgnf(xc) * norm_xy, ty = sgnf(yc) * norm_xy;
    const float FOPI = 1.2732395447351628f;
    float xq, yq;
    if (x_major) { xq = tx;                        yq = tx * FOPI * atanf(yc / xd); }
    else         { xq = ty * FOPI * atanf(xc / yd); yq = ty; }
    if (sq_xy < EPS) { xq = 0.f; yq = 0.f; }

    float c0 = (xq + 1.f) * 2.5f, c1 = (yq + 1.f) * 2.5f, c2 = (zc + 1.f) * 2.5f;
    float f0 = floorf(c0), f1 = floorf(c1), f2 = floorf(c2);
    int i0x = min(max((int)f0, 0), KSZ - 1);
    int i0y = min(max((int)f1, 0), KSZ - 1);
    int i0z = min(max((int)f2, 0), KSZ - 1);
    unsigned packed = (unsigned)i0x | ((unsigned)i0y << 8) | ((unsigned)i0z << 16) | (m << 24);
    g_pairs[idx] = make_float4(__uint_as_float(packed), c0 - f0, c1 - f1, c2 - f2);
}

__global__ void count_kernel(const void* __restrict__ nmask) {
    int j = blockIdx.x * blockDim.x + threadIdx.x;
    if (j >= NPTS) return;
    int s = 0;
#pragma unroll
    for (int k = 0; k < KNB; k++) s += (int)read_mask(nmask, j * KNB + k);
    g_cnt[j] = (float)s;
}

// ---------------- W transpose (layers 2/3), fp16 ----------------
__global__ void wsplit_kernel(const float* __restrict__ W, int Kd, int Cout, int ldap) {
    int idx = blockIdx.x * 256 + threadIdx.x;
    if (idx >= Cout * ldap) return;
    int o = idx / ldap, k = idx - o * ldap;
    float v = (k < Kd) ? W[(size_t)k * Cout + o] : 0.f;
    g_Wtf[(size_t)o * ldap + k] = __float2half_rn(v);
}

// ---------------- sort: per-point slot records sorted by cell (deterministic) -------------
// block = 256 thr = 8 warps, one point per warp. Counting sort of 256 (neighbor,corner)
// slots into cell order; serial lane-0 placement for determinism. rec = {w fp32 | n u16}.
__global__ void sort_kernel(const int* __restrict__ nidx) {
    __shared__ unsigned bins[8][224];
    __shared__ unsigned char cellS[8][256];
    __shared__ float wF[8][256];
    __shared__ unsigned short nS[8][32];
    int wid = threadIdx.x >> 5, lane = threadIdx.x & 31;
    int j = blockIdx.x * 8 + wid;
    if (j >= NPTS) return;
    for (int i = lane; i < 224; i += 32) bins[wid][i] = 0;
    nS[wid][lane] = (unsigned short)nidx[j * KNB + lane];
    __syncwarp();

    float4 p = g_pairs[j * KNB + lane];
    unsigned pk = __float_as_uint(p.x);
    int ix0 = pk & 255, iy0 = (pk >> 8) & 255, iz0 = (pk >> 16) & 255;
    float mk = (pk >> 24) ? 1.f : 0.f;
    int ix[2] = { ix0, min(ix0 + 1, KSZ - 1) };
    int iy[2] = { iy0, min(iy0 + 1, KSZ - 1) };
    int iz[2] = { iz0, min(iz0 + 1, KSZ - 1) };
    float wx[2] = { 1.f - p.y, p.y };
    float wy[2] = { 1.f - p.z, p.z };
    float wz[2] = { 1.f - p.w, p.w };
#pragma unroll
    for (int c8 = 0; c8 < 8; c8++) {
        int cx = c8 >> 2, cy = (c8 >> 1) & 1, cz = c8 & 1;
        int cell = (ix[cx] * KSZ + iy[cy]) * KSZ + iz[cz];
        cellS[wid][lane * 8 + c8] = (unsigned char)cell;
        wF[wid][lane * 8 + c8] = wx[cx] * wy[cy] * wz[cz] * mk;
        atomicAdd(&bins[wid][cell], 1u);
    }
    __syncwarp();

    unsigned carry = 0;
    for (int c = 0; c < 7; c++) {
        int idx = c * 32 + lane;
        unsigned v = (idx < MCELLS) ? bins[wid][idx] : 0;
        unsigned sc = v;
#pragma unroll
        for (int d = 1; d < 32; d <<= 1) {
            unsigned t = __shfl_up_sync(0xFFFFFFFFu, sc, d);
            if (lane >= d) sc += t;
        }
        if (idx < MCELLS) {
            unsigned excl = carry + sc - v;
            bins[wid][idx] = excl;
            g_offs[j * 218 + idx] = (unsigned short)excl;
        }
        carry += __shfl_sync(0xFFFFFFFFu, sc, 31);
    }
    if (lane == 0) g_offs[j * 218 + MCELLS] = 256;
    __syncwarp();

    if (lane == 0) {
        for (int s = 0; s < 256; s++) {
            int cell = cellS[wid][s];
            unsigned pos = bins[wid][cell]++;
            unsigned w32 = __float_as_uint(wF[wid][s]);
            g_recs[(size_t)j * 256 + pos] =
                ((unsigned long long)w32 << 32) | (unsigned)nS[wid][s >> 3];
        }
    }
}

// ---------------- layer-1 scatter (CIN=4, smem atomics, row-major fp16 A) ----------------
__global__ void scatter4_kernel(const float* __restrict__ X, const int* __restrict__ nidx) {
    const int CIN = 4;
    extern __shared__ float sm[];
    float* A    = sm;
    float* feat = A + MCELLS * CIN;
    float* wS   = feat + KNB * CIN;
    unsigned short* cellS = (unsigned short*)(wS + KNB * 8);

    int j = blockIdx.x;
    int tid = threadIdx.x;

    for (int i = tid; i < MCELLS * CIN; i += 256) A[i] = 0.f;
    for (int i = tid; i < KNB * CIN; i += 256) {
        int k = i / CIN, c = i - k * CIN;
        feat[i] = X[(size_t)nidx[j * KNB + k] * CIN + c];
    }
    if (tid < KNB) {
        float4 p = g_pairs[j * KNB + tid];
        unsigned pk = __float_as_uint(p.x);
        int ix0 = pk & 255, iy0 = (pk >> 8) & 255, iz0 = (pk >> 16) & 255;
        float mk = (pk >> 24) ? 1.f : 0.f;
        int ix[2] = { ix0, min(ix0 + 1, KSZ - 1) };
        int iy[2] = { iy0, min(iy0 + 1, KSZ - 1) };
        int iz[2] = { iz0, min(iz0 + 1, KSZ - 1) };
        float wx[2] = { 1.f - p.y, p.y };
        float wy[2] = { 1.f - p.z, p.z };
        float wz[2] = { 1.f - p.w, p.w };
#pragma unroll
        for (int c8 = 0; c8 < 8; c8++) {
            int cx = c8 >> 2, cy = (c8 >> 1) & 1, cz = c8 & 1;
            cellS[tid * 8 + c8] = (unsigned short)((ix[cx] * KSZ + iy[cy]) * KSZ + iz[cz]);
            wS[tid * 8 + c8] = wx[cx] * wy[cy] * wz[cz] * mk;
        }
    }
    __syncthreads();

    for (int base = 0; base < KNB * 8 * CIN; base += 256) {
        int idx = base + tid;
        int p = idx / CIN, c = idx - p * CIN;
        float w = wS[p];
        if (w != 0.f) atomicAdd(&A[cellS[p] * CIN + c], w * feat[(p >> 3) * CIN + c]);
    }
    __syncthreads();

    uint4* df = (uint4*)(g_Af + (size_t)j * LDA1);
    const int NV = MCELLS * CIN;
    for (int i = tid * 8; i < LDA1; i += 256 * 8) {
        uint32_t w[4];
#pragma unroll
        for (int p = 0; p < 4; p++) {
            int e = i + p * 2;
            float v0 = (e     < NV) ? A[e]     : 0.f;
            float v1 = (e + 1 < NV) ? A[e + 1] : 0.f;
            __half2 h2 = __floats2half2_rn(v0, v1);
            w[p] = *(uint32_t*)&h2;
        }
        __stcs(&df[i >> 3], make_uint4(w[0], w[1], w[2], w[3]));
    }
}

// ---------------- layer-1 persistent mma (row-major A from g_Af) ----------------
#define NSTG 4
#define STG 15360
#define OFF_B 10240

__launch_bounds__(256, 3)
__global__ void mma_kernel(int lda, int nch, int gridp) {
    extern __shared__ __align__(16) char smraw[];
    uint32_t sbase = smem_u32(smraw);
    int tid = threadIdx.x;
    int wid = tid >> 5, lane = tid & 31;
    const int NC = 64;

    int sel = lane >> 3, l8 = lane & 7;
    uint32_t aoff = (uint32_t)((wid * 16 + l8 + (sel & 1) * 8) * 80 + ((sel >> 1) * 8) * 2);
    uint32_t boff = (uint32_t)(((sel >> 1) * 8 + l8) * 80 + ((sel & 1) * 8) * 2);

    long total = (long)MT * nch;
    int g = blockIdx.x;
    int beg = (int)(total * g / gridp);
    int end = (int)(total * (g + 1) / gridp);
    int cnt = end - beg;
    if (cnt <= 0) return;

    float acc[8][4];
#pragma unroll
    for (int t = 0; t < 8; t++)
#pragma unroll
        for (int q = 0; q < 4; q++) acc[t][q] = 0.f;

    auto load_stage = [&](int widx, int s) {
        uint32_t st = sbase + s * STG;
        int mt = widx / nch, kc = widx - mt * nch;
        int m0 = mt * 128;
        size_t k0 = (size_t)kc * 32;
        for (int idx = tid; idx < 512; idx += 256) {
            int r = idx >> 2, sg = idx & 3;
            cpa16(st + r * 80 + sg * 16,
                  (const char*)(g_Af + (size_t)(m0 + r) * lda + k0) + sg * 16);
        }
        for (int idx = tid; idx < NC * 4; idx += 256) {
            int o = idx >> 2, sg = idx & 3;
            cpa16(st + OFF_B + o * 80 + sg * 16,
                  (const char*)(g_Wtf + (size_t)o * lda + k0) + sg * 16);
        }
        asm volatile("cp.async.commit_group;" ::: "memory");
    };

    auto compute = [&](int s) {
        uint32_t st = sbase + s * STG;
#pragma unroll
        for (int ks = 0; ks < 2; ks++) {
            uint32_t a[4];
            ldmx4(a, st + aoff + ks * 32);
#pragma unroll
            for (int ng = 0; ng < 4; ng++) {
                uint32_t b[4];
                ldmx4(b, st + OFF_B + boff + (uint32_t)(ng * 16 * 80) + ks * 32);
                mma16816h(acc[2 * ng],     a, b[0], b[1]);
                mma16816h(acc[2 * ng + 1], a, b[2], b[3]);
            }
        }
    };

    auto flush = [&](int mt) {
        int m0 = mt * 128;
        int gg = lane >> 2, tg = lane & 3;
        int r0 = m0 + wid * 16 + gg;
        int r1 = r0 + 8;
#pragma unroll
        for (int nt = 0; nt < 8; nt++) {
            int col = nt * 8 + tg * 2;
            if (r0 < NPTS) {
                atomicAdd(&g_acc[r0 * NC + col],     acc[nt][0]);
                atomicAdd(&g_acc[r0 * NC + col + 1], acc[nt][1]);
            }
            if (r1 < NPTS) {
                atomicAdd(&g_acc[r1 * NC + col],     acc[nt][2]);
                atomicAdd(&g_acc[r1 * NC + col + 1], acc[nt][3]);
            }
#pragma unroll
            for (int q = 0; q < 4; q++) acc[nt][q] = 0.f;
        }
    };

    int cur_mt = beg / nch;

    if (cnt < NSTG) {
        for (int p = 0; p < cnt; p++) load_stage(beg + p, p);
        asm volatile("cp.async.wait_group 0;" ::: "memory");
        __syncthreads();
        for (int i = 0; i < cnt; i++) {
            int mt = (beg + i) / nch;
            if (mt != cur_mt) { flush(cur_mt); cur_mt = mt; }
            compute(i);
        }
        flush(cur_mt);
        return;
    }

    for (int p = 0; p < NSTG - 1; p++) load_stage(beg + p, p);
    for (int i = 0; i < cnt; i++) {
        asm volatile("cp.async.wait_group %0;" :: "n"(NSTG - 2) : "memory");
        __syncthreads();
        int mt = (beg + i) / nch;
        if (mt != cur_mt) { flush(cur_mt); cur_mt = mt; }
        compute(i % NSTG);
        if (i + NSTG - 1 < cnt) load_stage(beg + i + NSTG - 1, (i + NSTG - 1) % NSTG);
        else asm volatile("cp.async.commit_group;" ::: "memory");
    }
    flush(cur_mt);
}

// ---------------- fused scatter+MMA (layers 2/3): A produced in smem, never in DRAM ------
// chunk kc -> cell kc/2, channels (kc&1)*32..+32. 256 threads: r=tid&127, hc=tid>>7 (16ch).
// A: 2 buffers x 128x80B. B: NSB-stage cp.async ring (L2-resident W).
#define NSB 4
#define ABUF_SZ 10240

template <int NC>
__launch_bounds__(256, 3)
__global__ void fused_kernel(int gridp) {
    extern __shared__ __align__(16) char smraw[];
    uint32_t sbase = smem_u32(smraw);
    uint32_t bbase = sbase + 2 * ABUF_SZ;
    const int BSTG = NC * 80;
    int tid = threadIdx.x;
    int wid = tid >> 5, lane = tid & 31;

    int sel = lane >> 3, l8 = lane & 7;
    uint32_t aoff = (uint32_t)((wid * 16 + l8 + (sel & 1) * 8) * 80 + ((sel >> 1) * 8) * 2);
    uint32_t boff = (uint32_t)(((sel >> 1) * 8 + l8) * 80 + ((sel & 1) * 8) * 2);

    long total = (long)MT * NCH2;
    int g = blockIdx.x;
    int beg = (int)(total * g / gridp);
    int end = (int)(total * (g + 1) / gridp);
    int cnt = end - beg;
    if (cnt <= 0) return;

    float acc[NC / 8][4];
#pragma unroll
    for (int t = 0; t < NC / 8; t++)
#pragma unroll
        for (int q = 0; q < 4; q++) acc[t][q] = 0.f;

    int pr = tid & 127, phc = tid >> 7;   // produce: row, channel-half

    auto produce = [&](int widx, int parity) {
        int mt = widx / NCH2, kc = widx - mt * NCH2;
        int j = mt * 128 + pr;
        int cell = kc >> 1;
        int ch0 = (kc & 1) * 32 + phc * 16;
        uint32_t h[8];
#pragma unroll
        for (int q = 0; q < 8; q++) h[q] = 0u;
        if (j < NPTS) {
            int s0 = g_offs[j * 218 + cell];
            int s1 = g_offs[j * 218 + cell + 1];
            for (int s = s0; s < s1; s++) {
                unsigned long long rec = __ldg(&g_recs[(size_t)j * 256 + s]);
                float w = __uint_as_float((unsigned)(rec >> 32));
                int n = (int)(rec & 0xFFFFu);
                const uint4* fp = (const uint4*)(g_Xh + (size_t)n * 64 + ch0);
                uint4 fa = __ldg(fp), fb = __ldg(fp + 1);
                __half2 w2 = __floats2half2_rn(w, w);
                const __half2* pa = (const __half2*)&fa;
                const __half2* pb = (const __half2*)&fb;
#pragma unroll
                for (int q = 0; q < 4; q++) {
                    __half2 hv = *(__half2*)&h[q];
                    hv = __hfma2(pa[q], w2, hv);
                    h[q] = *(uint32_t*)&hv;
                }
#pragma unroll
                for (int q = 0; q < 4; q++) {
                    __half2 hv = *(__half2*)&h[4 + q];
                    hv = __hfma2(pb[q], w2, hv);
                    h[4 + q] = *(uint32_t*)&hv;
                }
            }
        }
        uint32_t dst = sbase + parity * ABUF_SZ + (uint32_t)(pr * 80 + phc * 32);
        STS128A(dst, h[0], h[1], h[2], h[3]);
        STS128A(dst + 16, h[4], h[5], h[6], h[7]);
    };

    auto load_b = [&](int widx, int s) {
        int kc = widx % NCH2;
        size_t k0 = (size_t)kc * 32;
        uint32_t st = bbase + s * BSTG;
        for (int idx = tid; idx < NC * 4; idx += 256) {
            int o = idx >> 2, sg = idx & 3;
            cpa16(st + o * 80 + sg * 16,
                  (const char*)(g_Wtf + (size_t)o * KD2 + k0) + sg * 16);
        }
        asm volatile("cp.async.commit_group;" ::: "memory");
    };

    auto compute = [&](int parity, int bs) {
        uint32_t ast = sbase + parity * ABUF_SZ;
        uint32_t bst = bbase + bs * BSTG;
#pragma unroll
        for (int ks = 0; ks < 2; ks++) {
            uint32_t a[4];
            ldmx4(a, ast + aoff + ks * 32);
#pragma unroll
            for (int ng = 0; ng < NC / 16; ng++) {
                uint32_t b[4];
                ldmx4(b, bst + boff + (uint32_t)(ng * 16 * 80) + ks * 32);
                mma16816h(acc[2 * ng],     a, b[0], b[1]);
                mma16816h(acc[2 * ng + 1], a, b[2], b[3]);
            }
        }
    };

    auto flush = [&](int mt) {
        int m0 = mt * 128;
        int gg = lane >> 2, tg = lane & 3;
        int r0 = m0 + wid * 16 + gg;
        int r1 = r0 + 8;
#pragma unroll
        for (int nt = 0; nt < NC / 8; nt++) {
            int col = nt * 8 + tg * 2;
            if (r0 < NPTS) {
                atomicAdd(&g_acc[r0 * NC + col],     acc[nt][0]);
                atomicAdd(&g_acc[r0 * NC + col + 1], acc[nt][1]);
            }
            if (r1 < NPTS) {
                atomicAdd(&g_acc[r1 * NC + col],     acc[nt][2]);
                atomicAdd(&g_acc[r1 * NC + col + 1], acc[nt][3]);
            }
#pragma unroll
            for (int q = 0; q < 4; q++) acc[nt][q] = 0.f;
        }
    };

    int cur_mt = beg / NCH2;

    produce(beg, 0);
    int npre = (cnt < NSB - 1) ? cnt : (NSB - 1);
    for (int p = 0; p < npre; p++) load_b(beg + p, p);

    for (int i = 0; i < cnt; i++) {
        asm volatile("cp.async.wait_group %0;" :: "n"(NSB - 2) : "memory");
        __syncthreads();
        int mt = (beg + i) / NCH2;
        if (mt != cur_mt) { flush(cur_mt); cur_mt = mt; }
        compute(i & 1, i % NSB);
        if (i + 1 < cnt) produce(beg + i + 1, (i + 1) & 1);
        if (i + NSB - 1 < cnt) load_b(beg + i + NSB - 1, (i + NSB - 1) % NSB);
        else asm volatile("cp.async.commit_group;" ::: "memory");
    }
    flush(cur_mt);
}

// ---------------- finalize: normalize + bias + ReLU; re-zero g_acc for next layer --------
// dst_sel 1/2 -> g_Xh (fp16); 3 -> g_X3 + zero upper tail of g_acc
__global__ void finalize_kernel(const float* __restrict__ bias, int Cout, int dst_sel) {
    int idx = blockIdx.x * 256 + threadIdx.x;
    int lim = NPTS * Cout;
    if (dst_sel == 3 && idx >= lim) {            // zero-only tail
        if (idx < NPTS * 64) g_acc[idx] = 0.f;
        return;
    }
    if (idx >= lim) return;
    int j = idx / Cout, co = idx - j * Cout;
    float v = g_acc[idx];
    g_acc[idx] = 0.f;
    float c = g_cnt[j];
    if (c > 0.f) v /= c;
    v = fmaxf(v + bias[co], 0.f);
    if (dst_sel == 3) g_X3[idx] = v;
    else g_Xh[idx] = __float2half_rn(v);
}

// ---------------- fused FC chain: 32->64->64->32->3 ----------------
__global__ void fc_kernel(const float* __restrict__ Wf1, const float* __restrict__ bf1,
                          const float* __restrict__ Wf2, const float* __restrict__ bf2,
                          const float* __restrict__ Wf3, const float* __restrict__ bf3,
                          const float* __restrict__ Wo,  const float* __restrict__ bo,
                          float* __restrict__ out) {
    __shared__ float w1[32 * 64], w2[64 * 64], w3[64 * 32], wo[32 * 3];
    __shared__ float bb1[64], bb2[64], bb3[32], bbo[3];
    int tid = threadIdx.x;  // 128
    for (int i = tid; i < 2048; i += 128) w1[i] = Wf1[i];
    for (int i = tid; i < 4096; i += 128) w2[i] = Wf2[i];
    for (int i = tid; i < 2048; i += 128) w3[i] = Wf3[i];
    for (int i = tid; i < 96; i += 128) wo[i] = Wo[i];
    if (tid < 64) { bb1[tid] = bf1[tid]; bb2[tid] = bf2[tid]; }
    if (tid < 32) bb3[tid] = bf3[tid];
    if (tid < 3)  bbo[tid] = bo[tid];
    __syncthreads();

    int j = blockIdx.x * 128 + tid;
    if (j >= NPTS) return;

    float x[32];
#pragma unroll
    for (int i = 0; i < 32; i++) x[i] = g_X3[j * 32 + i];
    float y[64];
    for (int o = 0; o < 64; o++) {
        float s = bb1[o];
#pragma unroll
        for (int i = 0; i < 32; i++) s += x[i] * w1[i * 64 + o];
        y[o] = fmaxf(s, 0.f);
    }
    float z[64];
    for (int o = 0; o < 64; o++) {
        float s = bb2[o];
#pragma unroll
        for (int i = 0; i < 64; i++) s += y[i] * w2[i * 64 + o];
        z[o] = fmaxf(s, 0.f);
    }
    float t[32];
    for (int o = 0; o < 32; o++) {
        float s = bb3[o];
#pragma unroll
        for (int i = 0; i < 64; i++) s += z[i] * w3[i * 32 + o];
        t[o] = fmaxf(s, 0.f);
    }
    for (int o = 0; o < 3; o++) {
        float s = bbo[o];
#pragma unroll
        for (int i = 0; i < 32; i++) s += t[i] * wo[i * 3 + o];
        out[j * 3 + o] = s;
    }
}

// ---------------- launch ----------------
extern "C" void kernel_launch(void* const* d_in, const int* in_sizes, int n_in,
                              void* d_out, int out_size) {
    const float* feats = (const float*)d_in[0];
    const float* pos   = (const float*)d_in[1];
    const int*   nidx  = (const int*)d_in[2];
    const void*  nmask = d_in[3];
    const float* W1 = (const float*)d_in[4];  const float* b1 = (const float*)d_in[5];
    const float* W2 = (const float*)d_in[6];  const float* b2 = (const float*)d_in[7];
    const float* W3 = (const float*)d_in[8];  const float* b3 = (const float*)d_in[9];
    const float* Wf1 = (const float*)d_in[10]; const float* bf1 = (const float*)d_in[11];
    const float* Wf2 = (const float*)d_in[12]; const float* bf2 = (const float*)d_in[13];
    const float* Wf3 = (const float*)d_in[14]; const float* bf3 = (const float*)d_in[15];
    const float* Wo  = (const float*)d_in[16]; const float* bo  = (const float*)d_in[17];
    float* out = (float*)d_out;

    const int SMEM4 = (MCELLS * 4 + KNB * 4 + 256) * 4 + 512;
    const int SMEM_MMA = NSTG * STG;                     // 61440
    const int SMEM_F64 = 2 * ABUF_SZ + NSB * 64 * 80;    // 40960
    const int SMEM_F32 = 2 * ABUF_SZ + NSB * 32 * 80;    // 30720
    cudaFuncSetAttribute(scatter4_kernel, cudaFuncAttributeMaxDynamicSharedMemorySize, SMEM4);
    cudaFuncSetAttribute(mma_kernel, cudaFuncAttributeMaxDynamicSharedMemorySize, SMEM_MMA);
    cudaFuncSetAttribute(fused_kernel<64>, cudaFuncAttributeMaxDynamicSharedMemorySize, SMEM_F64);
    cudaFuncSetAttribute(fused_kernel<32>, cudaFuncAttributeMaxDynamicSharedMemorySize, SMEM_F32);

    int nsm = 148;
    cudaDeviceGetAttribute(&nsm, cudaDevAttrMultiProcessorCount, 0);
    int nbm = 1, nbf64 = 1, nbf32 = 1;
    cudaOccupancyMaxActiveBlocksPerMultiprocessor(&nbm, mma_kernel, 256, SMEM_MMA);
    cudaOccupancyMaxActiveBlocksPerMultiprocessor(&nbf64, fused_kernel<64>, 256, SMEM_F64);
    cudaOccupancyMaxActiveBlocksPerMultiprocessor(&nbf32, fused_kernel<32>, 256, SMEM_F32);
    if (nbm < 1) nbm = 1;
    if (nbf64 < 1) nbf64 = 1;
    if (nbf32 < 1) nbf32 = 1;
    int gridm = nbm * nsm, gridf64 = nbf64 * nsm, gridf32 = nbf32 * nsm;

    // ---- layer 1 ----
    detect_mask_kernel<<<(NPTS * KNB + 255) / 256, 256>>>((const unsigned char*)nmask);   // 0
    geom_kernel<<<(NPTS * KNB + 255) / 256, 256>>>(pos, nidx, nmask, W1);                 // 1 (+wsplit W1)
    scatter4_kernel<<<NPTS, 256, SMEM4>>>(feats, nidx);                                   // 2
    mma_kernel<<<gridm, 256, SMEM_MMA>>>(LDA1, LDA1 / 32, gridm);                         // 3 <- profiled
    sort_kernel<<<(NPTS + 7) / 8, 256>>>(nidx);                                           // 4
    count_kernel<<<(NPTS + 255) / 256, 256>>>(nmask);                                     // 5
    finalize_kernel<<<(NPTS * 64 + 255) / 256, 256>>>(b1, 64, 1);                         // -> g_Xh

    // ---- layer 2: fused scatter+mma, zero A DRAM traffic ----
    wsplit_kernel<<<(64 * KD2 + 255) / 256, 256>>>(W2, KD2, 64, KD2);
    fused_kernel<64><<<gridf64, 256, SMEM_F64>>>(gridf64);
    finalize_kernel<<<(NPTS * 64 + 255) / 256, 256>>>(b2, 64, 2);                         // -> g_Xh

    // ---- layer 3 ----
    wsplit_kernel<<<(32 * KD2 + 255) / 256, 256>>>(W3, KD2, 32, KD2);
    fused_kernel<32><<<gridf32, 256, SMEM_F32>>>(gridf32);
    finalize_kernel<<<(NPTS * 64 + 255) / 256, 256>>>(b3, 32, 3);                         // -> g_X3 (+zero tail)

    // FC head
    fc_kernel<<<(NPTS + 127) / 128, 128>>>(Wf1, bf1, Wf2, bf2, Wf3, bf3, Wo, bo, out);
}

// round 17
// speedup vs baseline: 1.6198x; 1.1551x over previous
#include <cuda_runtime.h>
#include <cuda_bf16.h>
#include <cuda_fp16.h>
#include <cstdint>

#define NPTS 10000
#define KNB 32
#define KSZ 6
#define MCELLS 216           // 6*6*6
#define KD2 (MCELLS * 64)    // 13824
#define LDA1 896             // layer1 Kd=864 padded to 28*32
#define RPAD 10112           // 79 tiles * 128 rows
#define MT 79                // M tiles

// ---------------- device scratch (static: no allocs allowed) ----------------
__device__ float4 g_pairs[NPTS * KNB];
__device__ float  g_cnt[NPTS];
__device__ __align__(16) __half g_Af[(size_t)RPAD * LDA1];  // layer-1 A fp16 (18 MB)
__device__ __align__(16) __half g_Wtf[64 * KD2];            // transposed W fp16 [Cout][lda]
__device__ __align__(16) __half g_Xh[NPTS * 64];            // activations fp16 (layer in/out)
__device__ float  g_acc[NPTS * 64];                         // fp32 accumulator (zeroed by finalize chain)
__device__ float  g_X3[NPTS * 32];
__device__ uint32_t g_offs32[NPTS * MCELLS];                // per (point,cell): start | end<<16
__device__ unsigned long long g_recs[NPTS * 256];           // sorted slot records {w fp32 | n u16}
__device__ int    g_mask_is_u8;

__device__ __forceinline__ float sgnf(float v) { return (v > 0.f) ? 1.f : ((v < 0.f) ? -1.f : 0.f); }

// ---------------- PTX helpers (all sm_80+ baseline; no 103a features) ----------------
__device__ __forceinline__ uint32_t smem_u32(const void* p) {
    uint32_t a;
    asm("{ .reg .u64 t; cvta.to.shared.u64 t, %1; cvt.u32.u64 %0, t; }" : "=r"(a) : "l"(p));
    return a;
}
__device__ __forceinline__ void cpa16(uint32_t dst, const void* src) {
    asm volatile("cp.async.cg.shared.global [%0], [%1], 16;" :: "r"(dst), "l"(src) : "memory");
}
#define STS128A(addr, a, b, c, d) \
    asm volatile("st.shared.v4.b32 [%0], {%1,%2,%3,%4};" :: "r"(addr), "r"(a), "r"(b), "r"(c), "r"(d) : "memory")
__device__ __forceinline__ void ldmx4(uint32_t* r, uint32_t addr) {
    asm volatile("ldmatrix.sync.aligned.m8n8.x4.shared.b16 {%0,%1,%2,%3}, [%4];"
                 : "=r"(r[0]), "=r"(r[1]), "=r"(r[2]), "=r"(r[3]) : "r"(addr));
}
__device__ __forceinline__ void mma16816h(float* d, const uint32_t* a, uint32_t b0, uint32_t b1) {
    asm volatile(
        "mma.sync.aligned.m16n8k16.row.col.f32.f16.f16.f32 "
        "{%0,%1,%2,%3}, {%4,%5,%6,%7}, {%8,%9}, {%0,%1,%2,%3};"
        : "+f"(d[0]), "+f"(d[1]), "+f"(d[2]), "+f"(d[3])
        : "r"(a[0]), "r"(a[1]), "r"(a[2]), "r"(a[3]), "r"(b0), "r"(b1));
}

// ---------------- mask dtype detection ----------------
__global__ void detect_mask_kernel(const unsigned char* __restrict__ bytes) {
    int i = blockIdx.x * 256 + threadIdx.x;
    if (i >= NPTS * KNB) return;
    if ((i & 3) != 0 && bytes[i] != 0) atomicOr(&g_mask_is_u8, 1);
}
__device__ __forceinline__ unsigned read_mask(const void* m, int idx) {
    if (g_mask_is_u8) return ((const unsigned char*)m)[idx] ? 1u : 0u;
    return ((const int*)m)[idx] ? 1u : 0u;
}

// ---------------- geometry (+ fused wsplit of W1) ----------------
__global__ void geom_kernel(const float* __restrict__ pos, const int* __restrict__ nidx,
                            const void* __restrict__ nmask, const float* __restrict__ W1) {
    int idx = blockIdx.x * blockDim.x + threadIdx.x;

    if (idx < 64 * LDA1) {
        int o = idx / LDA1, k = idx - o * LDA1;
        float v = (k < MCELLS * 4) ? W1[(size_t)k * 64 + o] : 0.f;
        g_Wtf[(size_t)o * LDA1 + k] = __float2half_rn(v);
    }

    if (idx >= NPTS * KNB) return;
    int j = idx >> 5;
    int n = nidx[idx];
    unsigned m = read_mask(nmask, idx);

    const float EPS = 1e-12f;
    float x = (pos[n * 3 + 0] - pos[j * 3 + 0]) * (2.0f / 3.0f);
    float y = (pos[n * 3 + 1] - pos[j * 3 + 1]) * (2.0f / 3.0f);
    float z = (pos[n * 3 + 2] - pos[j * 3 + 2]) * (2.0f / 3.0f);

    float sq = x * x + y * y + z * z;
    float norm = sqrtf(fmaxf(sq, EPS));
    float rho2 = x * x + y * y;
    bool in_cone = (1.25f * z * z > rho2);
    float s, zc;
    if (in_cone) { s = sqrtf(3.0f * norm / (norm + fabsf(z))); zc = sgnf(z) * norm; }
    else         { s = norm / sqrtf(fmaxf(rho2, EPS));         zc = 1.5f * z; }
    float xc = x * s, yc = y * s;
    if (sq < EPS) { xc = 0.f; yc = 0.f; zc = 0.f; }

    float sq_xy = xc * xc + yc * yc;
    float norm_xy = sqrtf(fmaxf(sq_xy, EPS));
    bool x_major = fabsf(yc) <= fabsf(xc);
    float xd = (fabsf(xc) < EPS) ? 1.f : xc;
    float yd = (fabsf(yc) < EPS) ? 1.f : yc;
    float tx = sgnf(xc) * norm_xy, ty = sgnf(yc) * norm_xy;
    const float FOPI = 1.2732395447351628f;
    float xq, yq;
    if (x_major) { xq = tx;                        yq = tx * FOPI * atanf(yc / xd); }
    else         { xq = ty * FOPI * atanf(xc / yd); yq = ty; }
    if (sq_xy < EPS) { xq = 0.f; yq = 0.f; }

    float c0 = (xq + 1.f) * 2.5f, c1 = (yq + 1.f) * 2.5f, c2 = (zc + 1.f) * 2.5f;
    float f0 = floorf(c0), f1 = floorf(c1), f2 = floorf(c2);
    int i0x = min(max((int)f0, 0), KSZ - 1);
    int i0y = min(max((int)f1, 0), KSZ - 1);
    int i0z = min(max((int)f2, 0), KSZ - 1);
    unsigned packed = (unsigned)i0x | ((unsigned)i0y << 8) | ((unsigned)i0z << 16) | (m << 24);
    g_pairs[idx] = make_float4(__uint_as_float(packed), c0 - f0, c1 - f1, c2 - f2);
}

// ---------------- W transpose (layers 2/3), fp16 ----------------
__global__ void wsplit_kernel(const float* __restrict__ W, int Kd, int Cout, int ldap) {
    int idx = blockIdx.x * 256 + threadIdx.x;
    if (idx >= Cout * ldap) return;
    int o = idx / ldap, k = idx - o * ldap;
    float v = (k < Kd) ? W[(size_t)k * Cout + o] : 0.f;
    g_Wtf[(size_t)o * ldap + k] = __float2half_rn(v);
}

// ---------------- sort: per-point slot records sorted by cell + neighbor count -----------
// block = 256 thr = 8 warps, one point per warp. rec = {w fp32 | n u16}.
// g_offs32[j*216+c] = start | (end << 16). Also writes g_cnt (mask popcount).
__global__ void sort_kernel(const int* __restrict__ nidx) {
    __shared__ unsigned bins[8][224];
    __shared__ unsigned char cellS[8][256];
    __shared__ float wF[8][256];
    __shared__ unsigned short nS[8][32];
    int wid = threadIdx.x >> 5, lane = threadIdx.x & 31;
    int j = blockIdx.x * 8 + wid;
    if (j >= NPTS) return;
    for (int i = lane; i < 224; i += 32) bins[wid][i] = 0;
    nS[wid][lane] = (unsigned short)nidx[j * KNB + lane];
    __syncwarp();

    float4 p = g_pairs[j * KNB + lane];
    unsigned pk = __float_as_uint(p.x);
    int ix0 = pk & 255, iy0 = (pk >> 8) & 255, iz0 = (pk >> 16) & 255;
    float mk = (pk >> 24) ? 1.f : 0.f;
    unsigned bal = __ballot_sync(0xFFFFFFFFu, (pk >> 24) != 0);
    if (lane == 0) g_cnt[j] = (float)__popc(bal);
    int ix[2] = { ix0, min(ix0 + 1, KSZ - 1) };
    int iy[2] = { iy0, min(iy0 + 1, KSZ - 1) };
    int iz[2] = { iz0, min(iz0 + 1, KSZ - 1) };
    float wx[2] = { 1.f - p.y, p.y };
    float wy[2] = { 1.f - p.z, p.z };
    float wz[2] = { 1.f - p.w, p.w };
#pragma unroll
    for (int c8 = 0; c8 < 8; c8++) {
        int cx = c8 >> 2, cy = (c8 >> 1) & 1, cz = c8 & 1;
        int cell = (ix[cx] * KSZ + iy[cy]) * KSZ + iz[cz];
        cellS[wid][lane * 8 + c8] = (unsigned char)cell;
        wF[wid][lane * 8 + c8] = wx[cx] * wy[cy] * wz[cz] * mk;
        atomicAdd(&bins[wid][cell], 1u);
    }
    __syncwarp();

    unsigned carry = 0;
    for (int c = 0; c < 7; c++) {
        int idx = c * 32 + lane;
        unsigned v = (idx < MCELLS) ? bins[wid][idx] : 0;
        unsigned sc = v;
#pragma unroll
        for (int d = 1; d < 32; d <<= 1) {
            unsigned t = __shfl_up_sync(0xFFFFFFFFu, sc, d);
            if (lane >= d) sc += t;
        }
        if (idx < MCELLS) {
            unsigned excl = carry + sc - v;
            bins[wid][idx] = excl;
            g_offs32[j * MCELLS + idx] = excl | ((excl + v) << 16);
        }
        carry += __shfl_sync(0xFFFFFFFFu, sc, 31);
    }
    __syncwarp();

    if (lane == 0) {
        for (int s = 0; s < 256; s++) {
            int cell = cellS[wid][s];
            unsigned pos = bins[wid][cell]++;
            unsigned w32 = __float_as_uint(wF[wid][s]);
            g_recs[(size_t)j * 256 + pos] =
                ((unsigned long long)w32 << 32) | (unsigned)nS[wid][s >> 3];
        }
    }
}

// ---------------- layer-1 scatter (CIN=4, smem atomics, row-major fp16 A) ----------------
__global__ void scatter4_kernel(const float* __restrict__ X, const int* __restrict__ nidx) {
    const int CIN = 4;
    extern __shared__ float sm[];
    float* A    = sm;
    float* feat = A + MCELLS * CIN;
    float* wS   = feat + KNB * CIN;
    unsigned short* cellS = (unsigned short*)(wS + KNB * 8);

    int j = blockIdx.x;
    int tid = threadIdx.x;

    for (int i = tid; i < MCELLS * CIN; i += 256) A[i] = 0.f;
    for (int i = tid; i < KNB * CIN; i += 256) {
        int k = i / CIN, c = i - k * CIN;
        feat[i] = X[(size_t)nidx[j * KNB + k] * CIN + c];
    }
    if (tid < KNB) {
        float4 p = g_pairs[j * KNB + tid];
        unsigned pk = __float_as_uint(p.x);
        int ix0 = pk & 255, iy0 = (pk >> 8) & 255, iz0 = (pk >> 16) & 255;
        float mk = (pk >> 24) ? 1.f : 0.f;
        int ix[2] = { ix0, min(ix0 + 1, KSZ - 1) };
        int iy[2] = { iy0, min(iy0 + 1, KSZ - 1) };
        int iz[2] = { iz0, min(iz0 + 1, KSZ - 1) };
        float wx[2] = { 1.f - p.y, p.y };
        float wy[2] = { 1.f - p.z, p.z };
        float wz[2] = { 1.f - p.w, p.w };
#pragma unroll
        for (int c8 = 0; c8 < 8; c8++) {
            int cx = c8 >> 2, cy = (c8 >> 1) & 1, cz = c8 & 1;
            cellS[tid * 8 + c8] = (unsigned short)((ix[cx] * KSZ + iy[cy]) * KSZ + iz[cz]);
            wS[tid * 8 + c8] = wx[cx] * wy[cy] * wz[cz] * mk;
        }
    }
    __syncthreads();

    for (int base = 0; base < KNB * 8 * CIN; base += 256) {
        int idx = base + tid;
        int p = idx / CIN, c = idx - p * CIN;
        float w = wS[p];
        if (w != 0.f) atomicAdd(&A[cellS[p] * CIN + c], w * feat[(p >> 3) * CIN + c]);
    }
    __syncthreads();

    uint4* df = (uint4*)(g_Af + (size_t)j * LDA1);
    const int NV = MCELLS * CIN;
    for (int i = tid * 8; i < LDA1; i += 256 * 8) {
        uint32_t w[4];
#pragma unroll
        for (int p = 0; p < 4; p++) {
            int e = i + p * 2;
            float v0 = (e     < NV) ? A[e]     : 0.f;
            float v1 = (e + 1 < NV) ? A[e + 1] : 0.f;
            __half2 h2 = __floats2half2_rn(v0, v1);
            w[p] = *(uint32_t*)&h2;
        }
        __stcs(&df[i >> 3], make_uint4(w[0], w[1], w[2], w[3]));
    }
}

// ---------------- layer-1 persistent mma (row-major A from g_Af) ----------------
#define NSTG 4
#define STG 15360
#define OFF_B 10240

__launch_bounds__(256, 3)
__global__ void mma_kernel(int lda, int nch, int gridp) {
    extern __shared__ __align__(16) char smraw[];
    uint32_t sbase = smem_u32(smraw);
    int tid = threadIdx.x;
    int wid = tid >> 5, lane = tid & 31;
    const int NC = 64;

    int sel = lane >> 3, l8 = lane & 7;
    uint32_t aoff = (uint32_t)((wid * 16 + l8 + (sel & 1) * 8) * 80 + ((sel >> 1) * 8) * 2);
    uint32_t boff = (uint32_t)(((sel >> 1) * 8 + l8) * 80 + ((sel & 1) * 8) * 2);

    long total = (long)MT * nch;
    int g = blockIdx.x;
    int beg = (int)(total * g / gridp);
    int end = (int)(total * (g + 1) / gridp);
    int cnt = end - beg;
    if (cnt <= 0) return;

    float acc[8][4];
#pragma unroll
    for (int t = 0; t < 8; t++)
#pragma unroll
        for (int q = 0; q < 4; q++) acc[t][q] = 0.f;

    auto load_stage = [&](int widx, int s) {
        uint32_t st = sbase + s * STG;
        int mt = widx / nch, kc = widx - mt * nch;
        int m0 = mt * 128;
        size_t k0 = (size_t)kc * 32;
        for (int idx = tid; idx < 512; idx += 256) {
            int r = idx >> 2, sg = idx & 3;
            cpa16(st + r * 80 + sg * 16,
                  (const char*)(g_Af + (size_t)(m0 + r) * lda + k0) + sg * 16);
        }
        for (int idx = tid; idx < NC * 4; idx += 256) {
            int o = idx >> 2, sg = idx & 3;
            cpa16(st + OFF_B + o * 80 + sg * 16,
                  (const char*)(g_Wtf + (size_t)o * lda + k0) + sg * 16);
        }
        asm volatile("cp.async.commit_group;" ::: "memory");
    };

    auto compute = [&](int s) {
        uint32_t st = sbase + s * STG;
#pragma unroll
        for (int ks = 0; ks < 2; ks++) {
            uint32_t a[4];
            ldmx4(a, st + aoff + ks * 32);
#pragma unroll
            for (int ng = 0; ng < 4; ng++) {
                uint32_t b[4];
                ldmx4(b, st + OFF_B + boff + (uint32_t)(ng * 16 * 80) + ks * 32);
                mma16816h(acc[2 * ng],     a, b[0], b[1]);
                mma16816h(acc[2 * ng + 1], a, b[2], b[3]);
            }
        }
    };

    auto flush = [&](int mt) {
        int m0 = mt * 128;
        int gg = lane >> 2, tg = lane & 3;
        int r0 = m0 + wid * 16 + gg;
        int r1 = r0 + 8;
#pragma unroll
        for (int nt = 0; nt < 8; nt++) {
            int col = nt * 8 + tg * 2;
            if (r0 < NPTS) {
                atomicAdd(&g_acc[r0 * NC + col],     acc[nt][0]);
                atomicAdd(&g_acc[r0 * NC + col + 1], acc[nt][1]);
            }
            if (r1 < NPTS) {
                atomicAdd(&g_acc[r1 * NC + col],     acc[nt][2]);
                atomicAdd(&g_acc[r1 * NC + col + 1], acc[nt][3]);
            }
#pragma unroll
            for (int q = 0; q < 4; q++) acc[nt][q] = 0.f;
        }
    };

    int cur_mt = beg / nch;

    if (cnt < NSTG) {
        for (int p = 0; p < cnt; p++) load_stage(beg + p, p);
        asm volatile("cp.async.wait_group 0;" ::: "memory");
        __syncthreads();
        for (int i = 0; i < cnt; i++) {
            int mt = (beg + i) / nch;
            if (mt != cur_mt) { flush(cur_mt); cur_mt = mt; }
            compute(i);
        }
        flush(cur_mt);
        return;
    }

    for (int p = 0; p < NSTG - 1; p++) load_stage(beg + p, p);
    for (int i = 0; i < cnt; i++) {
        asm volatile("cp.async.wait_group %0;" :: "n"(NSTG - 2) : "memory");
        __syncthreads();
        int mt = (beg + i) / nch;
        if (mt != cur_mt) { flush(cur_mt); cur_mt = mt; }
        compute(i % NSTG);
        if (i + NSTG - 1 < cnt) load_stage(beg + i + NSTG - 1, (i + NSTG - 1) % NSTG);
        else asm volatile("cp.async.commit_group;" ::: "memory");
    }
    flush(cur_mt);
}

// ---------------- fused scatter+MMA v2 (layers 2/3): cell-granular, pipelined produce ----
// Work item = (mtile, cell): 79*216 items. Per cell, produce BOTH 32-k chunks (full 64 ch)
// from one slot walk; records prefetched one cell ahead, offsets two ahead.
// A: 2 cells x 2 chunk bufs (4 x 10240 B). B: 2 cells x 2 chunks (2 x 2*NC*80 B).
#define ACELL 10240

template <int NC>
__launch_bounds__(256, 3)
__global__ void fused_kernel(int gridp) {
    extern __shared__ __align__(16) char smraw[];
    uint32_t abase = smem_u32(smraw);
    uint32_t bbase = abase + 4 * ACELL;
    const int BCELL = 2 * NC * 80;
    int tid = threadIdx.x;
    int wid = tid >> 5, lane = tid & 31;

    int sel = lane >> 3, l8 = lane & 7;
    uint32_t aoff = (uint32_t)((wid * 16 + l8 + (sel & 1) * 8) * 80 + ((sel >> 1) * 8) * 2);
    uint32_t boff = (uint32_t)(((sel >> 1) * 8 + l8) * 80 + ((sel & 1) * 8) * 2);

    const long total = (long)MT * MCELLS;
    int g = blockIdx.x;
    int beg = (int)(total * g / gridp);
    int end = (int)(total * (g + 1) / gridp);
    int n = end - beg;
    if (n <= 0) return;

    float acc[NC / 8][4];
#pragma unroll
    for (int t = 0; t < NC / 8; t++)
#pragma unroll
        for (int q = 0; q < 4; q++) acc[t][q] = 0.f;

    int pr = tid & 127, phc = tid >> 7;

    auto load_b = [&](int widx, int par) {
        int mt = widx / MCELLS;
        int cell = widx - mt * MCELLS;
        uint32_t bst = bbase + par * BCELL;
        for (int idx = tid; idx < NC * 8; idx += 256) {
            int o = idx >> 3, sg = idx & 7;
            int half = sg >> 2, sub = sg & 3;
            cpa16(bst + half * NC * 80 + o * 80 + sub * 16,
                  (const char*)(g_Wtf + (size_t)o * KD2 + cell * 64 + half * 32) + sub * 16);
        }
        asm volatile("cp.async.commit_group;" ::: "memory");
    };

    auto produce = [&](int j, int st, int en, unsigned long long r0,
                       unsigned long long r1, unsigned long long r2, int par) {
        uint32_t h[16];
#pragma unroll
        for (int q = 0; q < 16; q++) h[q] = 0u;
        if (j < NPTS) {
            int c = en - st;
            auto proc = [&](unsigned long long rec) {
                float w = __uint_as_float((unsigned)(rec >> 32));
                int nn = (int)(rec & 0xFFFFu);
                const uint4* fp = (const uint4*)(g_Xh + (size_t)nn * 64 + phc * 16);
                uint4 fa = __ldg(fp), fb = __ldg(fp + 1);
                const uint4* fq = (const uint4*)(g_Xh + (size_t)nn * 64 + 32 + phc * 16);
                uint4 fc = __ldg(fq), fd = __ldg(fq + 1);
                __half2 w2 = __floats2half2_rn(w, w);
                const __half2* pa = (const __half2*)&fa;
                const __half2* pb = (const __half2*)&fb;
                const __half2* pc = (const __half2*)&fc;
                const __half2* pd = (const __half2*)&fd;
#pragma unroll
                for (int q = 0; q < 4; q++) {
                    __half2 hv = *(__half2*)&h[q];      hv = __hfma2(pa[q], w2, hv); h[q] = *(uint32_t*)&hv;
                    __half2 hw = *(__half2*)&h[4 + q];  hw = __hfma2(pb[q], w2, hw); h[4 + q] = *(uint32_t*)&hw;
                    __half2 hx = *(__half2*)&h[8 + q];  hx = __hfma2(pc[q], w2, hx); h[8 + q] = *(uint32_t*)&hx;
                    __half2 hy = *(__half2*)&h[12 + q]; hy = __hfma2(pd[q], w2, hy); h[12 + q] = *(uint32_t*)&hy;
                }
            };
            if (c > 0) proc(r0);
            if (c > 1) proc(r1);
            if (c > 2) proc(r2);
            for (int s = st + 3; s < en; s++) proc(__ldg(&g_recs[(size_t)j * 256 + s]));
        }
        uint32_t d0 = abase + par * 2 * ACELL + (uint32_t)(pr * 80 + phc * 32);
        STS128A(d0, h[0], h[1], h[2], h[3]);
        STS128A(d0 + 16, h[4], h[5], h[6], h[7]);
        uint32_t d1 = d0 + ACELL;
        STS128A(d1, h[8], h[9], h[10], h[11]);
        STS128A(d1 + 16, h[12], h[13], h[14], h[15]);
    };

    auto compute = [&](int par, int half) {
        uint32_t ast = abase + par * 2 * ACELL + half * ACELL;
        uint32_t bst = bbase + par * BCELL + half * NC * 80;
#pragma unroll
        for (int ks = 0; ks < 2; ks++) {
            uint32_t a[4];
            ldmx4(a, ast + aoff + ks * 32);
#pragma unroll
            for (int ng = 0; ng < NC / 16; ng++) {
                uint32_t b[4];
                ldmx4(b, bst + boff + (uint32_t)(ng * 16 * 80) + ks * 32);
                mma16816h(acc[2 * ng],     a, b[0], b[1]);
                mma16816h(acc[2 * ng + 1], a, b[2], b[3]);
            }
        }
    };

    auto flush = [&](int mt) {
        int m0 = mt * 128;
        int gg = lane >> 2, tg = lane & 3;
        int r0 = m0 + wid * 16 + gg;
        int r1 = r0 + 8;
#pragma unroll
        for (int nt = 0; nt < NC / 8; nt++) {
            int col = nt * 8 + tg * 2;
            if (r0 < NPTS) {
                atomicAdd(&g_acc[r0 * NC + col],     acc[nt][0]);
                atomicAdd(&g_acc[r0 * NC + col + 1], acc[nt][1]);
            }
            if (r1 < NPTS) {
                atomicAdd(&g_acc[r1 * NC + col],     acc[nt][2]);
                atomicAdd(&g_acc[r1 * NC + col + 1], acc[nt][3]);
            }
#pragma unroll
            for (int q = 0; q < 4; q++) acc[nt][q] = 0.f;
        }
    };

    // prologue: offs+recs for cell beg (direct), offs for beg+1, B for beg
    int mt0 = beg / MCELLS, c0 = beg - mt0 * MCELLS;
    int j0 = mt0 * 128 + pr;
    int st = 0, en = 0;
    unsigned long long r0 = 0, r1 = 0, r2 = 0;
    if (j0 < NPTS) {
        uint32_t of = g_offs32[j0 * MCELLS + c0];
        st = of & 0xFFFF; en = of >> 16;
        if (st < en)     r0 = g_recs[(size_t)j0 * 256 + st];
        if (st + 1 < en) r1 = g_recs[(size_t)j0 * 256 + st + 1];
        if (st + 2 < en) r2 = g_recs[(size_t)j0 * 256 + st + 2];
    }
    load_b(beg, 0);
    uint32_t of_nxt = 0;
    if (n > 1) {
        int w1 = beg + 1;
        int mtn = w1 / MCELLS, cn = w1 - mtn * MCELLS;
        int jn = mtn * 128 + pr;
        if (jn < NPTS) of_nxt = g_offs32[jn * MCELLS + cn];
    }

    int cur_mt = mt0;
    for (int i = 0; i < n; i++) {
        int widx = beg + i;
        int mt = widx / MCELLS;
        int j = mt * 128 + pr;
        produce(j, st, en, r0, r1, r2, i & 1);

        // prefetch recs(i+1), offs(i+2)
        int stn = 0, enn = 0;
        unsigned long long p0 = 0, p1 = 0, p2 = 0;
        if (i + 1 < n) {
            int w1 = widx + 1;
            int mtn = w1 / MCELLS;
            int jn = mtn * 128 + pr;
            if (jn < NPTS) {
                stn = of_nxt & 0xFFFF; enn = of_nxt >> 16;
                if (stn < enn)     p0 = __ldg(&g_recs[(size_t)jn * 256 + stn]);
                if (stn + 1 < enn) p1 = __ldg(&g_recs[(size_t)jn * 256 + stn + 1]);
                if (stn + 2 < enn) p2 = __ldg(&g_recs[(size_t)jn * 256 + stn + 2]);
            }
        }
        uint32_t of2 = 0;
        if (i + 2 < n) {
            int w2 = widx + 2;
            int mt2 = w2 / MCELLS, cc = w2 - mt2 * MCELLS;
            int j2 = mt2 * 128 + pr;
            if (j2 < NPTS) of2 = __ldg(&g_offs32[j2 * MCELLS + cc]);
        }

        asm volatile("cp.async.wait_group 0;" ::: "memory");
        __syncthreads();
        if (i + 1 < n) load_b(widx + 1, (i + 1) & 1);
        if (mt != cur_mt) { flush(cur_mt); cur_mt = mt; }
        compute(i & 1, 0);
        compute(i & 1, 1);

        st = stn; en = enn; r0 = p0; r1 = p1; r2 = p2; of_nxt = of2;
    }
    flush(cur_mt);
}

// ---------------- finalize: normalize + bias + ReLU; re-zero g_acc for next layer --------
__global__ void finalize_kernel(const float* __restrict__ bias, int Cout, int dst_sel) {
    int idx = blockIdx.x * 256 + threadIdx.x;
    int lim = NPTS * Cout;
    if (dst_sel == 3 && idx >= lim) {
        if (idx < NPTS * 64) g_acc[idx] = 0.f;
        return;
    }
    if (idx >= lim) return;
    int j = idx / Cout, co = idx - j * Cout;
    float v = g_acc[idx];
    g_acc[idx] = 0.f;
    float c = g_cnt[j];
    if (c > 0.f) v /= c;
    v = fmaxf(v + bias[co], 0.f);
    if (dst_sel == 3) g_X3[idx] = v;
    else g_Xh[idx] = __float2half_rn(v);
}

// ---------------- fused FC chain: 32->64->64->32->3 ----------------
__global__ void fc_kernel(const float* __restrict__ Wf1, const float* __restrict__ bf1,
                          const float* __restrict__ Wf2, const float* __restrict__ bf2,
                          const float* __restrict__ Wf3, const float* __restrict__ bf3,
                          const float* __restrict__ Wo,  const float* __restrict__ bo,
                          float* __restrict__ out) {
    __shared__ float w1[32 * 64], w2[64 * 64], w3[64 * 32], wo[32 * 3];
    __shared__ float bb1[64], bb2[64], bb3[32], bbo[3];
    int tid = threadIdx.x;  // 128
    for (int i = tid; i < 2048; i += 128) w1[i] = Wf1[i];
    for (int i = tid; i < 4096; i += 128) w2[i] = Wf2[i];
    for (int i = tid; i < 2048; i += 128) w3[i] = Wf3[i];
    for (int i = tid; i < 96; i += 128) wo[i] = Wo[i];
    if (tid < 64) { bb1[tid] = bf1[tid]; bb2[tid] = bf2[tid]; }
    if (tid < 32) bb3[tid] = bf3[tid];
    if (tid < 3)  bbo[tid] = bo[tid];
    __syncthreads();

    int j = blockIdx.x * 128 + tid;
    if (j >= NPTS) return;

    float x[32];
#pragma unroll
    for (int i = 0; i < 32; i++) x[i] = g_X3[j * 32 + i];
    float y[64];
    for (int o = 0; o < 64; o++) {
        float s = bb1[o];
#pragma unroll
        for (int i = 0; i < 32; i++) s += x[i] * w1[i * 64 + o];
        y[o] = fmaxf(s, 0.f);
    }
    float z[64];
    for (int o = 0; o < 64; o++) {
        float s = bb2[o];
#pragma unroll
        for (int i = 0; i < 64; i++) s += y[i] * w2[i * 64 + o];
        z[o] = fmaxf(s, 0.f);
    }
    float t[32];
    for (int o = 0; o < 32; o++) {
        float s = bb3[o];
#pragma unroll
        for (int i = 0; i < 64; i++) s += z[i] * w3[i * 32 + o];
        t[o] = fmaxf(s, 0.f);
    }
    for (int o = 0; o < 3; o++) {
        float s = bbo[o];
#pragma unroll
        for (int i = 0; i < 32; i++) s += t[i] * wo[i * 3 + o];
        out[j * 3 + o] = s;
    }
}

// ---------------- launch ----------------
extern "C" void kernel_launch(void* const* d_in, const int* in_sizes, int n_in,
                              void* d_out, int out_size) {
    const float* feats = (const float*)d_in[0];
    const float* pos   = (const float*)d_in[1];
    const int*   nidx  = (const int*)d_in[2];
    const void*  nmask = d_in[3];
    const float* W1 = (const float*)d_in[4];  const float* b1 = (const float*)d_in[5];
    const float* W2 = (const float*)d_in[6];  const float* b2 = (const float*)d_in[7];
    const float* W3 = (const float*)d_in[8];  const float* b3 = (const float*)d_in[9];
    const float* Wf1 = (const float*)d_in[10]; const float* bf1 = (const float*)d_in[11];
    const float* Wf2 = (const float*)d_in[12]; const float* bf2 = (const float*)d_in[13];
    const float* Wf3 = (const float*)d_in[14]; const float* bf3 = (const float*)d_in[15];
    const float* Wo  = (const float*)d_in[16]; const float* bo  = (const float*)d_in[17];
    float* out = (float*)d_out;

    const int SMEM4 = (MCELLS * 4 + KNB * 4 + 256) * 4 + 512;
    const int SMEM_MMA = NSTG * STG;                     // 61440
    const int SMEM_F64 = 4 * ACELL + 2 * (2 * 64 * 80);  // 61440
    const int SMEM_F32 = 4 * ACELL + 2 * (2 * 32 * 80);  // 51200
    cudaFuncSetAttribute(scatter4_kernel, cudaFuncAttributeMaxDynamicSharedMemorySize, SMEM4);
    cudaFuncSetAttribute(mma_kernel, cudaFuncAttributeMaxDynamicSharedMemorySize, SMEM_MMA);
    cudaFuncSetAttribute(fused_kernel<64>, cudaFuncAttributeMaxDynamicSharedMemorySize, SMEM_F64);
    cudaFuncSetAttribute(fused_kernel<32>, cudaFuncAttributeMaxDynamicSharedMemorySize, SMEM_F32);

    int nsm = 148;
    cudaDeviceGetAttribute(&nsm, cudaDevAttrMultiProcessorCount, 0);
    int nbm = 1, nbf64 = 1, nbf32 = 1;
    cudaOccupancyMaxActiveBlocksPerMultiprocessor(&nbm, mma_kernel, 256, SMEM_MMA);
    cudaOccupancyMaxActiveBlocksPerMultiprocessor(&nbf64, fused_kernel<64>, 256, SMEM_F64);
    cudaOccupancyMaxActiveBlocksPerMultiprocessor(&nbf32, fused_kernel<32>, 256, SMEM_F32);
    if (nbm < 1) nbm = 1;
    if (nbf64 < 1) nbf64 = 1;
    if (nbf32 < 1) nbf32 = 1;
    int gridm = nbm * nsm, gridf64 = nbf64 * nsm, gridf32 = nbf32 * nsm;

    // ---- layer 1 ----
    detect_mask_kernel<<<(NPTS * KNB + 255) / 256, 256>>>((const unsigned char*)nmask);   // 0
    geom_kernel<<<(NPTS * KNB + 255) / 256, 256>>>(pos, nidx, nmask, W1);                 // 1 (+wsplit W1)
    scatter4_kernel<<<NPTS, 256, SMEM4>>>(feats, nidx);                                   // 2
    mma_kernel<<<gridm, 256, SMEM_MMA>>>(LDA1, LDA1 / 32, gridm);                         // 3 <- profiled
    sort_kernel<<<(NPTS + 7) / 8, 256>>>(nidx);                                           // 4 (+count)
    finalize_kernel<<<(NPTS * 64 + 255) / 256, 256>>>(b1, 64, 1);                         // -> g_Xh

    // ---- layer 2: fused scatter+mma (cell-pipelined) ----
    wsplit_kernel<<<(64 * KD2 + 255) / 256, 256>>>(W2, KD2, 64, KD2);
    fused_kernel<64><<<gridf64, 256, SMEM_F64>>>(gridf64);
    finalize_kernel<<<(NPTS * 64 + 255) / 256, 256>>>(b2, 64, 2);                         // -> g_Xh

    // ---- layer 3 ----
    wsplit_kernel<<<(32 * KD2 + 255) / 256, 256>>>(W3, KD2, 32, KD2);
    fused_kernel<32><<<gridf32, 256, SMEM_F32>>>(gridf32);
    finalize_kernel<<<(NPTS * 64 + 255) / 256, 256>>>(b3, 32, 3);                         // -> g_X3 (+zero tail)

    // FC head
    fc_kernel<<<(NPTS + 127) / 128, 128>>>(Wf1, bf1, Wf2, bf2, Wf3, bf3, Wo, bo, out);
}